// round 8
// baseline (speedup 1.0000x reference)
#include <cuda_runtime.h>
#include <cuda_bf16.h>
#include <math.h>

// ---------------- problem constants ----------------
#define DMODEL 768
#define NHEADS 12
#define DHEAD  64
#define DFF    3072
#define BBATCH 2
#define TSEQ   4096
#define MTOK   (BBATCH * TSEQ)   // 8192 tokens

// ---------------- scratch (device globals; no allocation allowed) ----------------
__device__ float g_Q  [MTOK * DMODEL];
__device__ float g_K  [MTOK * DMODEL];
__device__ float g_V  [MTOK * DMODEL];
__device__ float g_ATT[MTOK * DMODEL];
__device__ float g_R1 [MTOK * DMODEL];
__device__ float g_H  [MTOK * DMODEL];
__device__ float g_FF [MTOK * DFF];
__device__ float g_R2 [MTOK * DMODEL];

// =================================================================
// Generic fp32 GEMM: C[M,N] = A[M,K] @ W[K,N] + bias[N] (+res) (+relu)
// 128x128 tile, BK=16, 256 threads, 8x8 per thread.
// Requires M%128==0, N%128==0, K%16==0 (true for all our shapes).
// =================================================================
__global__ __launch_bounds__(256)
void gemm_kernel(const float* __restrict__ A, const float* __restrict__ W,
                 const float* __restrict__ bias, const float* __restrict__ res,
                 float* __restrict__ C, int M, int N, int K, int relu_flag)
{
    __shared__ float As[16][128];
    __shared__ float Ws[16][128];

    const int tid = threadIdx.x;
    const int bm  = blockIdx.y * 128;
    const int bn  = blockIdx.x * 128;
    const int tr  = tid >> 4;        // 0..15 -> rows tr*8..tr*8+7
    const int tc  = tid & 15;        // 0..15 -> cols tc*8..tc*8+7

    const int a_r = tid >> 2;        // 0..63
    const int a_c = (tid & 3) * 4;   // 0,4,8,12
    const int w_r = tid >> 5;        // 0..7
    const int w_c = (tid & 31) * 4;  // 0..124

    float acc[8][8];
#pragma unroll
    for (int i = 0; i < 8; i++)
#pragma unroll
        for (int j = 0; j < 8; j++) acc[i][j] = 0.f;

    const float* Ap = A + (size_t)bm * K;
    const float* Wp = W + bn;

    for (int k0 = 0; k0 < K; k0 += 16) {
        // load A tile 128x16 (transposed into As[k][m])
#pragma unroll
        for (int t = 0; t < 2; t++) {
            int r = a_r + t * 64;
            float4 v = *(const float4*)&Ap[(size_t)r * K + k0 + a_c];
            As[a_c + 0][r] = v.x;
            As[a_c + 1][r] = v.y;
            As[a_c + 2][r] = v.z;
            As[a_c + 3][r] = v.w;
        }
        // load W tile 16x128
#pragma unroll
        for (int t = 0; t < 2; t++) {
            int r = w_r + t * 8;
            float4 v = *(const float4*)&Wp[(size_t)(k0 + r) * N + w_c];
            *(float4*)&Ws[r][w_c] = v;
        }
        __syncthreads();

#pragma unroll
        for (int kk = 0; kk < 16; kk++) {
            float a[8], b[8];
            *(float4*)&a[0] = *(const float4*)&As[kk][tr * 8];
            *(float4*)&a[4] = *(const float4*)&As[kk][tr * 8 + 4];
            *(float4*)&b[0] = *(const float4*)&Ws[kk][tc * 8];
            *(float4*)&b[4] = *(const float4*)&Ws[kk][tc * 8 + 4];
#pragma unroll
            for (int i = 0; i < 8; i++)
#pragma unroll
                for (int j = 0; j < 8; j++)
                    acc[i][j] += a[i] * b[j];
        }
        __syncthreads();
    }

    // epilogue
#pragma unroll
    for (int i = 0; i < 8; i++) {
        int row = bm + tr * 8 + i;
        size_t base = (size_t)row * N + bn + tc * 8;
#pragma unroll
        for (int jv = 0; jv < 2; jv++) {
            float4 bv = *(const float4*)&bias[bn + tc * 8 + jv * 4];
            float4 o;
            o.x = acc[i][jv * 4 + 0] + bv.x;
            o.y = acc[i][jv * 4 + 1] + bv.y;
            o.z = acc[i][jv * 4 + 2] + bv.z;
            o.w = acc[i][jv * 4 + 3] + bv.w;
            if (res) {
                float4 rv = *(const float4*)&res[base + jv * 4];
                o.x += rv.x; o.y += rv.y; o.z += rv.z; o.w += rv.w;
            }
            if (relu_flag) {
                o.x = fmaxf(o.x, 0.f); o.y = fmaxf(o.y, 0.f);
                o.z = fmaxf(o.z, 0.f); o.w = fmaxf(o.w, 0.f);
            }
            *(float4*)&C[base + jv * 4] = o;
        }
    }
}

// =================================================================
// Flash attention (causal), fp32. One block = one (b, h, 64-query tile).
// 256 threads; each thread owns a 4x4 patch of the 64x64 S tile and a
// 4x4 patch of the 64x64 O tile. Streaming softmax over 64-key chunks.
// Layouts: Q/K/V are [MTOK, 768], head slice = 64 contiguous floats.
// =================================================================
#define QP 68   // Qs/Vs/Ps pitch (floats) - keeps float4 alignment, breaks bank patterns
#define KP 65   // K-transposed pitch
#define ATT_SMEM (3 * 64 * QP * 4)   // Qs + (Kt/Ps shared) + Vs, bytes

__global__ __launch_bounds__(256)
void attn_kernel(const float* __restrict__ Qg, const float* __restrict__ Kg,
                 const float* __restrict__ Vg, float* __restrict__ Og)
{
    extern __shared__ float sm[];
    float* Qs  = sm;                 // [64][QP]
    float* KtP = sm + 64 * QP;       // K transposed [64 d][KP] ; reused as P [64][QP]
    float* Vs  = sm + 2 * 64 * QP;   // [64][QP]

    const int q0 = blockIdx.x * 64;
    const int h  = blockIdx.y;
    const int b  = blockIdx.z;
    const int tid = threadIdx.x;
    const int tr = tid >> 4;            // row group 0..15
    const int tc = tid & 15;            // col group 0..15
    const int rbase = tr * 4;
    const int cbase = tc * 4;
    const float scale = 0.125f;         // 1/sqrt(64)

    // load Q tile (scaled)
    for (int i = tid; i < 64 * 16; i += 256) {
        int r  = i >> 4;
        int cv = (i & 15) * 4;
        float4 v = *(const float4*)&Qg[((size_t)(b * TSEQ + q0 + r)) * DMODEL + h * DHEAD + cv];
        float* d = &Qs[r * QP + cv];
        d[0] = v.x * scale; d[1] = v.y * scale; d[2] = v.z * scale; d[3] = v.w * scale;
    }

    float m_[4], l_[4], o_[4][4];
#pragma unroll
    for (int i = 0; i < 4; i++) {
        m_[i] = -1e30f; l_[i] = 0.f;
#pragma unroll
        for (int j = 0; j < 4; j++) o_[i][j] = 0.f;
    }

    for (int j0 = 0; j0 <= q0; j0 += 64) {
        __syncthreads();   // protect Kt/Ps/Vs from previous iteration readers

        // load K (transposed into [d][key]) and V (natural [key][d])
        for (int i = tid; i < 64 * 16; i += 256) {
            int r  = i >> 4;
            int cv = (i & 15) * 4;
            size_t g = ((size_t)(b * TSEQ + j0 + r)) * DMODEL + h * DHEAD + cv;
            float4 kv = *(const float4*)&Kg[g];
            KtP[(cv + 0) * KP + r] = kv.x;
            KtP[(cv + 1) * KP + r] = kv.y;
            KtP[(cv + 2) * KP + r] = kv.z;
            KtP[(cv + 3) * KP + r] = kv.w;
            float4 vv = *(const float4*)&Vg[g];
            *(float4*)&Vs[r * QP + cv] = vv;
        }
        __syncthreads();

        // S = Q K^T (scaled)
        float s[4][4];
#pragma unroll
        for (int i = 0; i < 4; i++)
#pragma unroll
            for (int j = 0; j < 4; j++) s[i][j] = 0.f;

#pragma unroll 8
        for (int kk = 0; kk < 64; kk++) {
            float a0 = Qs[(rbase + 0) * QP + kk];
            float a1 = Qs[(rbase + 1) * QP + kk];
            float a2 = Qs[(rbase + 2) * QP + kk];
            float a3 = Qs[(rbase + 3) * QP + kk];
            float b0 = KtP[kk * KP + cbase + 0];
            float b1 = KtP[kk * KP + cbase + 1];
            float b2 = KtP[kk * KP + cbase + 2];
            float b3 = KtP[kk * KP + cbase + 3];
            s[0][0] += a0 * b0; s[0][1] += a0 * b1; s[0][2] += a0 * b2; s[0][3] += a0 * b3;
            s[1][0] += a1 * b0; s[1][1] += a1 * b1; s[1][2] += a1 * b2; s[1][3] += a1 * b3;
            s[2][0] += a2 * b0; s[2][1] += a2 * b1; s[2][2] += a2 * b2; s[2][3] += a2 * b3;
            s[3][0] += a3 * b0; s[3][1] += a3 * b1; s[3][2] += a3 * b2; s[3][3] += a3 * b3;
        }

        // causal mask (only needed on the diagonal chunk)
        if (j0 == q0) {
#pragma unroll
            for (int i = 0; i < 4; i++)
#pragma unroll
                for (int j = 0; j < 4; j++)
                    if (j0 + cbase + j > q0 + rbase + i) s[i][j] = -1e30f;
        }

        // streaming softmax update (row groups of 16 lanes: same tr)
#pragma unroll
        for (int i = 0; i < 4; i++) {
            float cm = fmaxf(fmaxf(s[i][0], s[i][1]), fmaxf(s[i][2], s[i][3]));
#pragma unroll
            for (int off = 8; off; off >>= 1)
                cm = fmaxf(cm, __shfl_xor_sync(0xffffffffu, cm, off));
            float mn = fmaxf(m_[i], cm);
            float corr = __expf(m_[i] - mn);
            m_[i] = mn;
            float rs = 0.f;
#pragma unroll
            for (int j = 0; j < 4; j++) {
                float p = __expf(s[i][j] - mn);
                s[i][j] = p;
                rs += p;
            }
#pragma unroll
            for (int off = 8; off; off >>= 1)
                rs += __shfl_xor_sync(0xffffffffu, rs, off);
            l_[i] = l_[i] * corr + rs;
#pragma unroll
            for (int j = 0; j < 4; j++) o_[i][j] *= corr;
        }

        __syncthreads();   // everyone is done reading KtP as K
        // write P into the KtP buffer (now used as Ps[64][QP])
#pragma unroll
        for (int i = 0; i < 4; i++) {
            float4 p4 = make_float4(s[i][0], s[i][1], s[i][2], s[i][3]);
            *(float4*)&KtP[(rbase + i) * QP + cbase] = p4;
        }
        __syncthreads();

        // O += P @ V
#pragma unroll 8
        for (int kk = 0; kk < 64; kk++) {
            float p0 = KtP[(rbase + 0) * QP + kk];
            float p1 = KtP[(rbase + 1) * QP + kk];
            float p2 = KtP[(rbase + 2) * QP + kk];
            float p3 = KtP[(rbase + 3) * QP + kk];
            float4 v4 = *(const float4*)&Vs[kk * QP + cbase];
            o_[0][0] += p0 * v4.x; o_[0][1] += p0 * v4.y; o_[0][2] += p0 * v4.z; o_[0][3] += p0 * v4.w;
            o_[1][0] += p1 * v4.x; o_[1][1] += p1 * v4.y; o_[1][2] += p1 * v4.z; o_[1][3] += p1 * v4.w;
            o_[2][0] += p2 * v4.x; o_[2][1] += p2 * v4.y; o_[2][2] += p2 * v4.z; o_[2][3] += p2 * v4.w;
            o_[3][0] += p3 * v4.x; o_[3][1] += p3 * v4.y; o_[3][2] += p3 * v4.z; o_[3][3] += p3 * v4.w;
        }
    }

    // final normalize + write (merge heads: [MTOK, 768])
#pragma unroll
    for (int i = 0; i < 4; i++) {
        float invl = 1.f / l_[i];
        int q = q0 + rbase + i;
        size_t base = ((size_t)(b * TSEQ + q)) * DMODEL + h * DHEAD + cbase;
        float4 o4 = make_float4(o_[i][0] * invl, o_[i][1] * invl,
                                o_[i][2] * invl, o_[i][3] * invl);
        *(float4*)&Og[base] = o4;
    }
}

// =================================================================
// LayerNorm over last dim (768). One block (256 threads) per row.
// =================================================================
__global__ __launch_bounds__(256)
void ln_kernel(const float* __restrict__ in, const float* __restrict__ g,
               const float* __restrict__ be, float* __restrict__ out)
{
    const int row = blockIdx.x;
    const int tid = threadIdx.x;
    const float* xr = in + (size_t)row * DMODEL;

    float v0 = xr[tid];
    float v1 = xr[tid + 256];
    float v2 = xr[tid + 512];
    float s  = v0 + v1 + v2;
    float s2 = v0 * v0 + v1 * v1 + v2 * v2;

    __shared__ float rs[8], rs2[8], stats[2];
#pragma unroll
    for (int off = 16; off; off >>= 1) {
        s  += __shfl_xor_sync(0xffffffffu, s,  off);
        s2 += __shfl_xor_sync(0xffffffffu, s2, off);
    }
    int w = tid >> 5, lane = tid & 31;
    if (lane == 0) { rs[w] = s; rs2[w] = s2; }
    __syncthreads();
    if (tid == 0) {
        float S = 0.f, S2 = 0.f;
#pragma unroll
        for (int i = 0; i < 8; i++) { S += rs[i]; S2 += rs2[i]; }
        float mean = S * (1.f / DMODEL);
        float var  = S2 * (1.f / DMODEL) - mean * mean;
        stats[0] = mean;
        stats[1] = rsqrtf(var + 1e-5f);
    }
    __syncthreads();
    float mean = stats[0], r = stats[1];
    float* orow = out + (size_t)row * DMODEL;
    orow[tid]       = (v0 - mean) * r * g[tid]       + be[tid];
    orow[tid + 256] = (v1 - mean) * r * g[tid + 256] + be[tid + 256];
    orow[tid + 512] = (v2 - mean) * r * g[tid + 512] + be[tid + 512];
}

// =================================================================
// Host launch
// =================================================================
extern "C" void kernel_launch(void* const* d_in, const int* in_sizes, int n_in,
                              void* d_out, int out_size)
{
    const float* x  = (const float*)d_in[0];
    const float* wq = (const float*)d_in[1];
    const float* bq = (const float*)d_in[2];
    const float* wk = (const float*)d_in[3];
    const float* bk = (const float*)d_in[4];
    const float* wv = (const float*)d_in[5];
    const float* bv = (const float*)d_in[6];
    const float* wo = (const float*)d_in[7];
    const float* bo = (const float*)d_in[8];
    const float* w1 = (const float*)d_in[9];
    const float* b1 = (const float*)d_in[10];
    const float* w2 = (const float*)d_in[11];
    const float* b2 = (const float*)d_in[12];
    const float* g1 = (const float*)d_in[13];
    const float* be1= (const float*)d_in[14];
    const float* g2 = (const float*)d_in[15];
    const float* be2= (const float*)d_in[16];
    float* out = (float*)d_out;

    float *Q, *K, *V, *ATT, *R1, *H, *FF, *R2;
    cudaGetSymbolAddress((void**)&Q,   g_Q);
    cudaGetSymbolAddress((void**)&K,   g_K);
    cudaGetSymbolAddress((void**)&V,   g_V);
    cudaGetSymbolAddress((void**)&ATT, g_ATT);
    cudaGetSymbolAddress((void**)&R1,  g_R1);
    cudaGetSymbolAddress((void**)&H,   g_H);
    cudaGetSymbolAddress((void**)&FF,  g_FF);
    cudaGetSymbolAddress((void**)&R2,  g_R2);

    cudaFuncSetAttribute(attn_kernel, cudaFuncAttributeMaxDynamicSharedMemorySize, ATT_SMEM);

    dim3 gD(DMODEL / 128, MTOK / 128);   // (6, 64)
    dim3 gF(DFF / 128,    MTOK / 128);   // (24, 64)

    // QKV projections
    gemm_kernel<<<gD, 256>>>(x, wq, bq, nullptr, Q, MTOK, DMODEL, DMODEL, 0);
    gemm_kernel<<<gD, 256>>>(x, wk, bk, nullptr, K, MTOK, DMODEL, DMODEL, 0);
    gemm_kernel<<<gD, 256>>>(x, wv, bv, nullptr, V, MTOK, DMODEL, DMODEL, 0);

    // causal flash attention
    attn_kernel<<<dim3(TSEQ / 64, NHEADS, BBATCH), 256, ATT_SMEM>>>(Q, K, V, ATT);

    // output projection + residual, LN1
    gemm_kernel<<<gD, 256>>>(ATT, wo, bo, x, R1, MTOK, DMODEL, DMODEL, 0);
    ln_kernel<<<MTOK, 256>>>(R1, g1, be1, H);

    // FFN
    gemm_kernel<<<gF, 256>>>(H, w1, b1, nullptr, FF, MTOK, DFF, DMODEL, 1);
    gemm_kernel<<<gD, 256>>>(FF, w2, b2, H, R2, MTOK, DMODEL, DFF, 0);

    // LN2 -> output
    ln_kernel<<<MTOK, 256>>>(R2, g2, be2, out);
}

// round 9
// speedup vs baseline: 1.0049x; 1.0049x over previous
#include <cuda_runtime.h>
#include <cuda_bf16.h>
#include <math.h>

// ---------------- problem constants ----------------
#define DMODEL 768
#define NHEADS 12
#define DHEAD  64
#define DFF    3072
#define BBATCH 2
#define TSEQ   4096
#define MTOK   (BBATCH * TSEQ)   // 8192 tokens

// ---------------- scratch (device globals; no allocation allowed) ----------------
__device__ float g_Q  [MTOK * DMODEL];
__device__ float g_K  [MTOK * DMODEL];
__device__ float g_V  [MTOK * DMODEL];
__device__ float g_ATT[MTOK * DMODEL];
__device__ float g_R1 [MTOK * DMODEL];
__device__ float g_H  [MTOK * DMODEL];
__device__ float g_FF [MTOK * DFF];
__device__ float g_R2 [MTOK * DMODEL];

// =================================================================
// Generic fp32 GEMM: C[M,N] = A[M,K] @ W[K,N] + bias[N] (+res) (+relu)
// 128x128 tile, BK=16, 256 threads, 8x8 per thread.
// Requires M%128==0, N%128==0, K%16==0 (true for all our shapes).
// =================================================================
__global__ __launch_bounds__(256)
void gemm_kernel(const float* __restrict__ A, const float* __restrict__ W,
                 const float* __restrict__ bias, const float* __restrict__ res,
                 float* __restrict__ C, int M, int N, int K, int relu_flag)
{
    __shared__ float As[16][128];
    __shared__ float Ws[16][128];

    const int tid = threadIdx.x;
    const int bm  = blockIdx.y * 128;
    const int bn  = blockIdx.x * 128;
    const int tr  = tid >> 4;        // 0..15 -> rows tr*8..tr*8+7
    const int tc  = tid & 15;        // 0..15 -> cols tc*8..tc*8+7

    const int a_r = tid >> 2;        // 0..63
    const int a_c = (tid & 3) * 4;   // 0,4,8,12
    const int w_r = tid >> 5;        // 0..7
    const int w_c = (tid & 31) * 4;  // 0..124

    float acc[8][8];
#pragma unroll
    for (int i = 0; i < 8; i++)
#pragma unroll
        for (int j = 0; j < 8; j++) acc[i][j] = 0.f;

    const float* Ap = A + (size_t)bm * K;
    const float* Wp = W + bn;

    for (int k0 = 0; k0 < K; k0 += 16) {
        // load A tile 128x16 (transposed into As[k][m])
#pragma unroll
        for (int t = 0; t < 2; t++) {
            int r = a_r + t * 64;
            float4 v = *(const float4*)&Ap[(size_t)r * K + k0 + a_c];
            As[a_c + 0][r] = v.x;
            As[a_c + 1][r] = v.y;
            As[a_c + 2][r] = v.z;
            As[a_c + 3][r] = v.w;
        }
        // load W tile 16x128
#pragma unroll
        for (int t = 0; t < 2; t++) {
            int r = w_r + t * 8;
            float4 v = *(const float4*)&Wp[(size_t)(k0 + r) * N + w_c];
            *(float4*)&Ws[r][w_c] = v;
        }
        __syncthreads();

#pragma unroll
        for (int kk = 0; kk < 16; kk++) {
            float a[8], b[8];
            *(float4*)&a[0] = *(const float4*)&As[kk][tr * 8];
            *(float4*)&a[4] = *(const float4*)&As[kk][tr * 8 + 4];
            *(float4*)&b[0] = *(const float4*)&Ws[kk][tc * 8];
            *(float4*)&b[4] = *(const float4*)&Ws[kk][tc * 8 + 4];
#pragma unroll
            for (int i = 0; i < 8; i++)
#pragma unroll
                for (int j = 0; j < 8; j++)
                    acc[i][j] += a[i] * b[j];
        }
        __syncthreads();
    }

    // epilogue
#pragma unroll
    for (int i = 0; i < 8; i++) {
        int row = bm + tr * 8 + i;
        size_t base = (size_t)row * N + bn + tc * 8;
#pragma unroll
        for (int jv = 0; jv < 2; jv++) {
            float4 bv = *(const float4*)&bias[bn + tc * 8 + jv * 4];
            float4 o;
            o.x = acc[i][jv * 4 + 0] + bv.x;
            o.y = acc[i][jv * 4 + 1] + bv.y;
            o.z = acc[i][jv * 4 + 2] + bv.z;
            o.w = acc[i][jv * 4 + 3] + bv.w;
            if (res) {
                float4 rv = *(const float4*)&res[base + jv * 4];
                o.x += rv.x; o.y += rv.y; o.z += rv.z; o.w += rv.w;
            }
            if (relu_flag) {
                o.x = fmaxf(o.x, 0.f); o.y = fmaxf(o.y, 0.f);
                o.z = fmaxf(o.z, 0.f); o.w = fmaxf(o.w, 0.f);
            }
            *(float4*)&C[base + jv * 4] = o;
        }
    }
}

// =================================================================
// Flash attention (causal), fp32. One block = one (b, h, 64-query tile).
// 256 threads; each thread owns a 4x4 patch of the 64x64 S tile and a
// 4x4 patch of the 64x64 O tile. Streaming softmax over 64-key chunks.
// Layouts: Q/K/V are [MTOK, 768], head slice = 64 contiguous floats.
// =================================================================
#define QP 68   // Qs/Vs/Ps pitch (floats) - keeps float4 alignment, breaks bank patterns
#define KP 65   // K-transposed pitch
#define ATT_SMEM (3 * 64 * QP * 4)   // Qs + (Kt/Ps shared) + Vs, bytes

__global__ __launch_bounds__(256)
void attn_kernel(const float* __restrict__ Qg, const float* __restrict__ Kg,
                 const float* __restrict__ Vg, float* __restrict__ Og)
{
    extern __shared__ float sm[];
    float* Qs  = sm;                 // [64][QP]
    float* KtP = sm + 64 * QP;       // K transposed [64 d][KP] ; reused as P [64][QP]
    float* Vs  = sm + 2 * 64 * QP;   // [64][QP]

    const int q0 = blockIdx.x * 64;
    const int h  = blockIdx.y;
    const int b  = blockIdx.z;
    const int tid = threadIdx.x;
    const int tr = tid >> 4;            // row group 0..15
    const int tc = tid & 15;            // col group 0..15
    const int rbase = tr * 4;
    const int cbase = tc * 4;
    const float scale = 0.125f;         // 1/sqrt(64)

    // load Q tile (scaled)
    for (int i = tid; i < 64 * 16; i += 256) {
        int r  = i >> 4;
        int cv = (i & 15) * 4;
        float4 v = *(const float4*)&Qg[((size_t)(b * TSEQ + q0 + r)) * DMODEL + h * DHEAD + cv];
        float* d = &Qs[r * QP + cv];
        d[0] = v.x * scale; d[1] = v.y * scale; d[2] = v.z * scale; d[3] = v.w * scale;
    }

    float m_[4], l_[4], o_[4][4];
#pragma unroll
    for (int i = 0; i < 4; i++) {
        m_[i] = -1e30f; l_[i] = 0.f;
#pragma unroll
        for (int j = 0; j < 4; j++) o_[i][j] = 0.f;
    }

    for (int j0 = 0; j0 <= q0; j0 += 64) {
        __syncthreads();   // protect Kt/Ps/Vs from previous iteration readers

        // load K (transposed into [d][key]) and V (natural [key][d])
        for (int i = tid; i < 64 * 16; i += 256) {
            int r  = i >> 4;
            int cv = (i & 15) * 4;
            size_t g = ((size_t)(b * TSEQ + j0 + r)) * DMODEL + h * DHEAD + cv;
            float4 kv = *(const float4*)&Kg[g];
            KtP[(cv + 0) * KP + r] = kv.x;
            KtP[(cv + 1) * KP + r] = kv.y;
            KtP[(cv + 2) * KP + r] = kv.z;
            KtP[(cv + 3) * KP + r] = kv.w;
            float4 vv = *(const float4*)&Vg[g];
            *(float4*)&Vs[r * QP + cv] = vv;
        }
        __syncthreads();

        // S = Q K^T (scaled)
        float s[4][4];
#pragma unroll
        for (int i = 0; i < 4; i++)
#pragma unroll
            for (int j = 0; j < 4; j++) s[i][j] = 0.f;

#pragma unroll 8
        for (int kk = 0; kk < 64; kk++) {
            float a0 = Qs[(rbase + 0) * QP + kk];
            float a1 = Qs[(rbase + 1) * QP + kk];
            float a2 = Qs[(rbase + 2) * QP + kk];
            float a3 = Qs[(rbase + 3) * QP + kk];
            float b0 = KtP[kk * KP + cbase + 0];
            float b1 = KtP[kk * KP + cbase + 1];
            float b2 = KtP[kk * KP + cbase + 2];
            float b3 = KtP[kk * KP + cbase + 3];
            s[0][0] += a0 * b0; s[0][1] += a0 * b1; s[0][2] += a0 * b2; s[0][3] += a0 * b3;
            s[1][0] += a1 * b0; s[1][1] += a1 * b1; s[1][2] += a1 * b2; s[1][3] += a1 * b3;
            s[2][0] += a2 * b0; s[2][1] += a2 * b1; s[2][2] += a2 * b2; s[2][3] += a2 * b3;
            s[3][0] += a3 * b0; s[3][1] += a3 * b1; s[3][2] += a3 * b2; s[3][3] += a3 * b3;
        }

        // causal mask (only needed on the diagonal chunk)
        if (j0 == q0) {
#pragma unroll
            for (int i = 0; i < 4; i++)
#pragma unroll
                for (int j = 0; j < 4; j++)
                    if (j0 + cbase + j > q0 + rbase + i) s[i][j] = -1e30f;
        }

        // streaming softmax update (row groups of 16 lanes: same tr)
#pragma unroll
        for (int i = 0; i < 4; i++) {
            float cm = fmaxf(fmaxf(s[i][0], s[i][1]), fmaxf(s[i][2], s[i][3]));
#pragma unroll
            for (int off = 8; off; off >>= 1)
                cm = fmaxf(cm, __shfl_xor_sync(0xffffffffu, cm, off));
            float mn = fmaxf(m_[i], cm);
            float corr = __expf(m_[i] - mn);
            m_[i] = mn;
            float rs = 0.f;
#pragma unroll
            for (int j = 0; j < 4; j++) {
                float p = __expf(s[i][j] - mn);
                s[i][j] = p;
                rs += p;
            }
#pragma unroll
            for (int off = 8; off; off >>= 1)
                rs += __shfl_xor_sync(0xffffffffu, rs, off);
            l_[i] = l_[i] * corr + rs;
#pragma unroll
            for (int j = 0; j < 4; j++) o_[i][j] *= corr;
        }

        __syncthreads();   // everyone is done reading KtP as K
        // write P into the KtP buffer (now used as Ps[64][QP])
#pragma unroll
        for (int i = 0; i < 4; i++) {
            float4 p4 = make_float4(s[i][0], s[i][1], s[i][2], s[i][3]);
            *(float4*)&KtP[(rbase + i) * QP + cbase] = p4;
        }
        __syncthreads();

        // O += P @ V
#pragma unroll 8
        for (int kk = 0; kk < 64; kk++) {
            float p0 = KtP[(rbase + 0) * QP + kk];
            float p1 = KtP[(rbase + 1) * QP + kk];
            float p2 = KtP[(rbase + 2) * QP + kk];
            float p3 = KtP[(rbase + 3) * QP + kk];
            float4 v4 = *(const float4*)&Vs[kk * QP + cbase];
            o_[0][0] += p0 * v4.x; o_[0][1] += p0 * v4.y; o_[0][2] += p0 * v4.z; o_[0][3] += p0 * v4.w;
            o_[1][0] += p1 * v4.x; o_[1][1] += p1 * v4.y; o_[1][2] += p1 * v4.z; o_[1][3] += p1 * v4.w;
            o_[2][0] += p2 * v4.x; o_[2][1] += p2 * v4.y; o_[2][2] += p2 * v4.z; o_[2][3] += p2 * v4.w;
            o_[3][0] += p3 * v4.x; o_[3][1] += p3 * v4.y; o_[3][2] += p3 * v4.z; o_[3][3] += p3 * v4.w;
        }
    }

    // final normalize + write (merge heads: [MTOK, 768])
#pragma unroll
    for (int i = 0; i < 4; i++) {
        float invl = 1.f / l_[i];
        int q = q0 + rbase + i;
        size_t base = ((size_t)(b * TSEQ + q)) * DMODEL + h * DHEAD + cbase;
        float4 o4 = make_float4(o_[i][0] * invl, o_[i][1] * invl,
                                o_[i][2] * invl, o_[i][3] * invl);
        *(float4*)&Og[base] = o4;
    }
}

// =================================================================
// LayerNorm over last dim (768). One block (256 threads) per row.
// =================================================================
__global__ __launch_bounds__(256)
void ln_kernel(const float* __restrict__ in, const float* __restrict__ g,
               const float* __restrict__ be, float* __restrict__ out)
{
    const int row = blockIdx.x;
    const int tid = threadIdx.x;
    const float* xr = in + (size_t)row * DMODEL;

    float v0 = xr[tid];
    float v1 = xr[tid + 256];
    float v2 = xr[tid + 512];
    float s  = v0 + v1 + v2;
    float s2 = v0 * v0 + v1 * v1 + v2 * v2;

    __shared__ float rs[8], rs2[8], stats[2];
#pragma unroll
    for (int off = 16; off; off >>= 1) {
        s  += __shfl_xor_sync(0xffffffffu, s,  off);
        s2 += __shfl_xor_sync(0xffffffffu, s2, off);
    }
    int w = tid >> 5, lane = tid & 31;
    if (lane == 0) { rs[w] = s; rs2[w] = s2; }
    __syncthreads();
    if (tid == 0) {
        float S = 0.f, S2 = 0.f;
#pragma unroll
        for (int i = 0; i < 8; i++) { S += rs[i]; S2 += rs2[i]; }
        float mean = S * (1.f / DMODEL);
        float var  = S2 * (1.f / DMODEL) - mean * mean;
        stats[0] = mean;
        stats[1] = rsqrtf(var + 1e-5f);
    }
    __syncthreads();
    float mean = stats[0], r = stats[1];
    float* orow = out + (size_t)row * DMODEL;
    orow[tid]       = (v0 - mean) * r * g[tid]       + be[tid];
    orow[tid + 256] = (v1 - mean) * r * g[tid + 256] + be[tid + 256];
    orow[tid + 512] = (v2 - mean) * r * g[tid + 512] + be[tid + 512];
}

// =================================================================
// Host launch
// =================================================================
extern "C" void kernel_launch(void* const* d_in, const int* in_sizes, int n_in,
                              void* d_out, int out_size)
{
    const float* x  = (const float*)d_in[0];
    const float* wq = (const float*)d_in[1];
    const float* bq = (const float*)d_in[2];
    const float* wk = (const float*)d_in[3];
    const float* bk = (const float*)d_in[4];
    const float* wv = (const float*)d_in[5];
    const float* bv = (const float*)d_in[6];
    const float* wo = (const float*)d_in[7];
    const float* bo = (const float*)d_in[8];
    const float* w1 = (const float*)d_in[9];
    const float* b1 = (const float*)d_in[10];
    const float* w2 = (const float*)d_in[11];
    const float* b2 = (const float*)d_in[12];
    const float* g1 = (const float*)d_in[13];
    const float* be1= (const float*)d_in[14];
    const float* g2 = (const float*)d_in[15];
    const float* be2= (const float*)d_in[16];
    float* out = (float*)d_out;

    float *Q, *K, *V, *ATT, *R1, *H, *FF, *R2;
    cudaGetSymbolAddress((void**)&Q,   g_Q);
    cudaGetSymbolAddress((void**)&K,   g_K);
    cudaGetSymbolAddress((void**)&V,   g_V);
    cudaGetSymbolAddress((void**)&ATT, g_ATT);
    cudaGetSymbolAddress((void**)&R1,  g_R1);
    cudaGetSymbolAddress((void**)&H,   g_H);
    cudaGetSymbolAddress((void**)&FF,  g_FF);
    cudaGetSymbolAddress((void**)&R2,  g_R2);

    cudaFuncSetAttribute(attn_kernel, cudaFuncAttributeMaxDynamicSharedMemorySize, ATT_SMEM);

    dim3 gD(DMODEL / 128, MTOK / 128);   // (6, 64)
    dim3 gF(DFF / 128,    MTOK / 128);   // (24, 64)

    // QKV projections
    gemm_kernel<<<gD, 256>>>(x, wq, bq, nullptr, Q, MTOK, DMODEL, DMODEL, 0);
    gemm_kernel<<<gD, 256>>>(x, wk, bk, nullptr, K, MTOK, DMODEL, DMODEL, 0);
    gemm_kernel<<<gD, 256>>>(x, wv, bv, nullptr, V, MTOK, DMODEL, DMODEL, 0);

    // causal flash attention
    attn_kernel<<<dim3(TSEQ / 64, NHEADS, BBATCH), 256, ATT_SMEM>>>(Q, K, V, ATT);

    // output projection + residual, LN1
    gemm_kernel<<<gD, 256>>>(ATT, wo, bo, x, R1, MTOK, DMODEL, DMODEL, 0);
    ln_kernel<<<MTOK, 256>>>(R1, g1, be1, H);

    // FFN
    gemm_kernel<<<gF, 256>>>(H, w1, b1, nullptr, FF, MTOK, DFF, DMODEL, 1);
    gemm_kernel<<<gD, 256>>>(FF, w2, b2, H, R2, MTOK, DMODEL, DFF, 0);

    // LN2 -> output
    ln_kernel<<<MTOK, 256>>>(R2, g2, be2, out);
}

// round 11
// speedup vs baseline: 1.6547x; 1.6466x over previous
#include <cuda_runtime.h>
#include <cuda_bf16.h>
#include <stdint.h>
#include <math.h>

// ---------------- problem constants ----------------
#define DMODEL 768
#define NHEADS 12
#define DHEAD  64
#define DFF    3072
#define BBATCH 2
#define TSEQ   4096
#define MTOK   (BBATCH * TSEQ)   // 8192 tokens

// weight (transposed [N,K], bf16 hi/lo) offsets inside g_bhi/g_blo
#define WQ_OFF 0
#define WK_OFF (768*768)
#define WV_OFF (2*768*768)
#define WO_OFF (3*768*768)
#define W1_OFF (4*768*768)                 // [3072][768]
#define W2_OFF (4*768*768 + 768*3072)      // [768][3072]
#define WTOT   (4*768*768 + 2*768*3072)

// ---------------- scratch (device globals; no allocation allowed) ----------------
__device__ float g_Q  [MTOK * DMODEL];
__device__ float g_K  [MTOK * DMODEL];
__device__ float g_V  [MTOK * DMODEL];
__device__ float g_R1 [MTOK * DMODEL];
__device__ float g_H  [MTOK * DMODEL];
__device__ float g_R2 [MTOK * DMODEL];
__device__ __nv_bfloat16 g_ahi [MTOK * DMODEL];
__device__ __nv_bfloat16 g_alo [MTOK * DMODEL];
__device__ __nv_bfloat16 g_ffhi[MTOK * DFF];
__device__ __nv_bfloat16 g_fflo[MTOK * DFF];
__device__ __nv_bfloat16 g_bhi [WTOT];
__device__ __nv_bfloat16 g_blo [WTOT];

// ---------------- helpers ----------------
__device__ __forceinline__ uint32_t smem_u32(const void* p) {
    uint32_t a;
    asm("{ .reg .u64 t; cvta.to.shared.u64 t, %1; cvt.u32.u64 %0, t; }" : "=r"(a) : "l"(p));
    return a;
}
__device__ __forceinline__ void cp16(uint32_t d, const void* s) {
    asm volatile("cp.async.cg.shared.global [%0], [%1], 16;" :: "r"(d), "l"(s));
}
#define CP_COMMIT() asm volatile("cp.async.commit_group;" ::: "memory")
#define CP_WAIT0()  asm volatile("cp.async.wait_group 0;"  ::: "memory")
#define CP_WAIT1()  asm volatile("cp.async.wait_group 1;"  ::: "memory")

#define LDSM4(r0, r1, r2, r3, addr) \
    asm volatile("ldmatrix.sync.aligned.m8n8.x4.shared.b16 {%0,%1,%2,%3}, [%4];" \
        : "=r"(r0), "=r"(r1), "=r"(r2), "=r"(r3) : "r"(addr))

#define MMA16816(c, a, b) \
    asm volatile("mma.sync.aligned.m16n8k16.row.col.f32.bf16.bf16.f32 " \
        "{%0,%1,%2,%3},{%4,%5,%6,%7},{%8,%9},{%0,%1,%2,%3};" \
        : "+f"((c)[0]), "+f"((c)[1]), "+f"((c)[2]), "+f"((c)[3]) \
        : "r"((a)[0]), "r"((a)[1]), "r"((a)[2]), "r"((a)[3]), \
          "r"((b)[0]), "r"((b)[1]))

__device__ __forceinline__ void split_store(float v, __nv_bfloat16* hi, __nv_bfloat16* lo) {
    __nv_bfloat16 h = __float2bfloat16(v);
    *hi = h;
    *lo = __float2bfloat16(v - __bfloat162float(h));
}

// =================================================================
// mma.sync GEMM: C[M,N] = A[M,K] @ Bt[N,K]^T (+bias)(+res)(+relu)
// A,Bt given as bf16 hi/lo (both K-major). D = AhiBhi + AhiBlo + AloBhi,
// fp32 accumulation. Block 128x128, BK=32, 256 threads (8 warps, 64x32 each).
// Double-buffered cp.async pipeline. Rows padded to 40 bf16 (80B) in smem.
// =================================================================
#define BKG   32
#define ROWB  80                      // smem row stride, bytes (32 bf16 + 8 pad)
#define TILEB 10240                   // one 128-row tile, bytes (128*80)
#define STAGEB (4 * TILEB)            // Ah, Al, Bh, Bl
#define GEMM_SMEM (2 * STAGEB)        // 81920 B

__device__ __forceinline__ void load_stage(
    uint32_t st, const __nv_bfloat16* Ah, const __nv_bfloat16* Al,
    const __nv_bfloat16* Bh, const __nv_bfloat16* Bl,
    int bm, int bn, int k0, int K, int tid)
{
#pragma unroll
    for (int i = 0; i < 2; i++) {
        int c = tid + i * 256;           // 0..511
        int r = c >> 2;                  // row 0..127
        int kc = (c & 3) * 8;            // k element offset 0/8/16/24
        uint32_t so = (uint32_t)(r * ROWB + kc * 2);
        size_t goA = (size_t)(bm + r) * K + k0 + kc;
        size_t goB = (size_t)(bn + r) * K + k0 + kc;
        cp16(st + so,             Ah + goA);
        cp16(st + TILEB + so,     Al + goA);
        cp16(st + 2 * TILEB + so, Bh + goB);
        cp16(st + 3 * TILEB + so, Bl + goB);
    }
}

__global__ __launch_bounds__(256, 1)
void gemm_mma(const __nv_bfloat16* __restrict__ Ah, const __nv_bfloat16* __restrict__ Al,
              const __nv_bfloat16* __restrict__ Bh, const __nv_bfloat16* __restrict__ Bl,
              const float* __restrict__ bias, const float* __restrict__ res,
              float* __restrict__ C, __nv_bfloat16* __restrict__ Chi,
              __nv_bfloat16* __restrict__ Clo, int N, int K, int relu)
{
    extern __shared__ char smem[];
    const uint32_t sb = smem_u32(smem);
    const int tid = threadIdx.x;
    const int wid = tid >> 5, lane = tid & 31;
    const int wm = wid & 1;          // 0/1 -> 64-row half
    const int wn = wid >> 1;         // 0..3 -> 32-col quarter
    const int bm = blockIdx.y * 128, bn = blockIdx.x * 128;

    float acc[4][4][4];
#pragma unroll
    for (int mt = 0; mt < 4; mt++)
#pragma unroll
        for (int nt = 0; nt < 4; nt++)
#pragma unroll
            for (int i = 0; i < 4; i++) acc[mt][nt][i] = 0.f;

    const int nk = K / BKG;
    load_stage(sb, Ah, Al, Bh, Bl, bm, bn, 0, K, tid);
    CP_COMMIT();

    for (int ks = 0; ks < nk; ks++) {
        if (ks + 1 < nk) {
            load_stage(sb + ((ks + 1) & 1) * STAGEB, Ah, Al, Bh, Bl,
                       bm, bn, (ks + 1) * BKG, K, tid);
            CP_COMMIT();
            CP_WAIT1();
        } else {
            CP_WAIT0();
        }
        __syncthreads();

        const uint32_t st = sb + (ks & 1) * STAGEB;
#pragma unroll
        for (int kk = 0; kk < 2; kk++) {
            // A fragments (hi & lo): 4 m-tiles of 16 rows
            uint32_t ah[4][4], al[4][4];
            uint32_t aoff = st + (uint32_t)((wm * 64 + (lane & 15)) * ROWB)
                          + kk * 32 + ((lane >> 4) & 1) * 16;
#pragma unroll
            for (int mt = 0; mt < 4; mt++) {
                LDSM4(ah[mt][0], ah[mt][1], ah[mt][2], ah[mt][3], aoff + mt * 16 * ROWB);
                LDSM4(al[mt][0], al[mt][1], al[mt][2], al[mt][3], aoff + TILEB + mt * 16 * ROWB);
            }
            // B fragments (hi & lo): x4 gives two 8-col n-tiles at once
            uint32_t bh[4][2], bl[4][2];
            uint32_t boff = st + 2 * TILEB
                          + (uint32_t)((wn * 32 + (lane & 7) + ((lane >> 4) & 1) * 8) * ROWB)
                          + kk * 32 + ((lane >> 3) & 1) * 16;
#pragma unroll
            for (int np = 0; np < 2; np++) {
                uint32_t r0, r1, r2, r3;
                LDSM4(r0, r1, r2, r3, boff + np * 16 * ROWB);
                bh[2*np][0] = r0; bh[2*np][1] = r1; bh[2*np+1][0] = r2; bh[2*np+1][1] = r3;
                LDSM4(r0, r1, r2, r3, boff + TILEB + np * 16 * ROWB);
                bl[2*np][0] = r0; bl[2*np][1] = r1; bl[2*np+1][0] = r2; bl[2*np+1][1] = r3;
            }
#pragma unroll
            for (int mt = 0; mt < 4; mt++)
#pragma unroll
                for (int nt = 0; nt < 4; nt++) {
                    MMA16816(acc[mt][nt], ah[mt], bh[nt]);
                    MMA16816(acc[mt][nt], ah[mt], bl[nt]);
                    MMA16816(acc[mt][nt], al[mt], bh[nt]);
                }
        }
        __syncthreads();
    }

    // epilogue: fragment (mt,nt): c0,c1 at (row, col..col+1); c2,c3 at (row+8, ...)
#pragma unroll
    for (int mt = 0; mt < 4; mt++)
#pragma unroll
        for (int nt = 0; nt < 4; nt++) {
            int row = bm + wm * 64 + mt * 16 + (lane >> 2);
            int col = bn + wn * 32 + nt * 8 + (lane & 3) * 2;
            float b0 = bias[col], b1 = bias[col + 1];
#pragma unroll
            for (int half = 0; half < 2; half++) {
                int r = row + half * 8;
                size_t idx = (size_t)r * N + col;
                float v0 = acc[mt][nt][half * 2 + 0] + b0;
                float v1 = acc[mt][nt][half * 2 + 1] + b1;
                if (res) {
                    float2 rv = *(const float2*)&res[idx];
                    v0 += rv.x; v1 += rv.y;
                }
                if (relu) { v0 = fmaxf(v0, 0.f); v1 = fmaxf(v1, 0.f); }
                if (C) { float2 o = make_float2(v0, v1); *(float2*)&C[idx] = o; }
                if (Chi) {
                    __nv_bfloat16 h0 = __float2bfloat16(v0);
                    __nv_bfloat16 h1 = __float2bfloat16(v1);
                    __nv_bfloat162 hp; hp.x = h0; hp.y = h1;
                    *(__nv_bfloat162*)&Chi[idx] = hp;
                    __nv_bfloat162 lp;
                    lp.x = __float2bfloat16(v0 - __bfloat162float(h0));
                    lp.y = __float2bfloat16(v1 - __bfloat162float(h1));
                    *(__nv_bfloat162*)&Clo[idx] = lp;
                }
            }
        }
}

// =================================================================
// Weight transpose + split: W[K,N] fp32 -> Th/Tl[N,K] bf16
// =================================================================
__global__ void wsplit_kernel(const float* __restrict__ W, __nv_bfloat16* __restrict__ Th,
                              __nv_bfloat16* __restrict__ Tl, int Kd, int Nd)
{
    __shared__ float t[32][33];
    int k0 = blockIdx.x * 32, n0 = blockIdx.y * 32;
    int tx = threadIdx.x, ty = threadIdx.y;
    for (int i = ty; i < 32; i += 8)
        t[i][tx] = W[(size_t)(k0 + i) * Nd + n0 + tx];
    __syncthreads();
    for (int i = ty; i < 32; i += 8) {
        float v = t[tx][i];
        size_t o = (size_t)(n0 + i) * Kd + k0 + tx;
        split_store(v, &Th[o], &Tl[o]);
    }
}

__global__ void asplit_kernel(const float* __restrict__ A, __nv_bfloat16* __restrict__ Ah,
                              __nv_bfloat16* __restrict__ Al)
{
    int i = (blockIdx.x * blockDim.x + threadIdx.x) * 4;
    float4 v = *(const float4*)&A[i];
    split_store(v.x, &Ah[i + 0], &Al[i + 0]);
    split_store(v.y, &Ah[i + 1], &Al[i + 1]);
    split_store(v.z, &Ah[i + 2], &Al[i + 2]);
    split_store(v.w, &Ah[i + 3], &Al[i + 3]);
}

// =================================================================
// Flash attention (causal), fp32; epilogue emits bf16 hi/lo.
// =================================================================
#define QP 68
#define KP 65
#define ATT_SMEM (3 * 64 * QP * 4)

__global__ __launch_bounds__(256)
void attn_kernel(const float* __restrict__ Qg, const float* __restrict__ Kg,
                 const float* __restrict__ Vg, __nv_bfloat16* __restrict__ Oh,
                 __nv_bfloat16* __restrict__ Ol)
{
    extern __shared__ float sm[];
    float* Qs  = sm;
    float* KtP = sm + 64 * QP;
    float* Vs  = sm + 2 * 64 * QP;

    const int q0 = blockIdx.x * 64;
    const int h  = blockIdx.y;
    const int b  = blockIdx.z;
    const int tid = threadIdx.x;
    const int tr = tid >> 4, tc = tid & 15;
    const int rbase = tr * 4, cbase = tc * 4;
    const float scale = 0.125f;

    for (int i = tid; i < 64 * 16; i += 256) {
        int r = i >> 4, cv = (i & 15) * 4;
        float4 v = *(const float4*)&Qg[((size_t)(b * TSEQ + q0 + r)) * DMODEL + h * DHEAD + cv];
        float* d = &Qs[r * QP + cv];
        d[0] = v.x * scale; d[1] = v.y * scale; d[2] = v.z * scale; d[3] = v.w * scale;
    }

    float m_[4], l_[4], o_[4][4];
#pragma unroll
    for (int i = 0; i < 4; i++) {
        m_[i] = -1e30f; l_[i] = 0.f;
#pragma unroll
        for (int j = 0; j < 4; j++) o_[i][j] = 0.f;
    }

    for (int j0 = 0; j0 <= q0; j0 += 64) {
        __syncthreads();
        for (int i = tid; i < 64 * 16; i += 256) {
            int r = i >> 4, cv = (i & 15) * 4;
            size_t g = ((size_t)(b * TSEQ + j0 + r)) * DMODEL + h * DHEAD + cv;
            float4 kv = *(const float4*)&Kg[g];
            KtP[(cv + 0) * KP + r] = kv.x;
            KtP[(cv + 1) * KP + r] = kv.y;
            KtP[(cv + 2) * KP + r] = kv.z;
            KtP[(cv + 3) * KP + r] = kv.w;
            float4 vv = *(const float4*)&Vg[g];
            *(float4*)&Vs[r * QP + cv] = vv;
        }
        __syncthreads();

        float s[4][4];
#pragma unroll
        for (int i = 0; i < 4; i++)
#pragma unroll
            for (int j = 0; j < 4; j++) s[i][j] = 0.f;

#pragma unroll 8
        for (int kk = 0; kk < 64; kk++) {
            float a0 = Qs[(rbase + 0) * QP + kk];
            float a1 = Qs[(rbase + 1) * QP + kk];
            float a2 = Qs[(rbase + 2) * QP + kk];
            float a3 = Qs[(rbase + 3) * QP + kk];
            float b0 = KtP[kk * KP + cbase + 0];
            float b1 = KtP[kk * KP + cbase + 1];
            float b2 = KtP[kk * KP + cbase + 2];
            float b3 = KtP[kk * KP + cbase + 3];
            s[0][0] += a0 * b0; s[0][1] += a0 * b1; s[0][2] += a0 * b2; s[0][3] += a0 * b3;
            s[1][0] += a1 * b0; s[1][1] += a1 * b1; s[1][2] += a1 * b2; s[1][3] += a1 * b3;
            s[2][0] += a2 * b0; s[2][1] += a2 * b1; s[2][2] += a2 * b2; s[2][3] += a2 * b3;
            s[3][0] += a3 * b0; s[3][1] += a3 * b1; s[3][2] += a3 * b2; s[3][3] += a3 * b3;
        }

        if (j0 == q0) {
#pragma unroll
            for (int i = 0; i < 4; i++)
#pragma unroll
                for (int j = 0; j < 4; j++)
                    if (j0 + cbase + j > q0 + rbase + i) s[i][j] = -1e30f;
        }

#pragma unroll
        for (int i = 0; i < 4; i++) {
            float cm = fmaxf(fmaxf(s[i][0], s[i][1]), fmaxf(s[i][2], s[i][3]));
#pragma unroll
            for (int off = 8; off; off >>= 1)
                cm = fmaxf(cm, __shfl_xor_sync(0xffffffffu, cm, off));
            float mn = fmaxf(m_[i], cm);
            float corr = __expf(m_[i] - mn);
            m_[i] = mn;
            float rs = 0.f;
#pragma unroll
            for (int j = 0; j < 4; j++) {
                float p = __expf(s[i][j] - mn);
                s[i][j] = p;
                rs += p;
            }
#pragma unroll
            for (int off = 8; off; off >>= 1)
                rs += __shfl_xor_sync(0xffffffffu, rs, off);
            l_[i] = l_[i] * corr + rs;
#pragma unroll
            for (int j = 0; j < 4; j++) o_[i][j] *= corr;
        }

        __syncthreads();
#pragma unroll
        for (int i = 0; i < 4; i++)
            *(float4*)&KtP[(rbase + i) * QP + cbase] =
                make_float4(s[i][0], s[i][1], s[i][2], s[i][3]);
        __syncthreads();

#pragma unroll 8
        for (int kk = 0; kk < 64; kk++) {
            float p0 = KtP[(rbase + 0) * QP + kk];
            float p1 = KtP[(rbase + 1) * QP + kk];
            float p2 = KtP[(rbase + 2) * QP + kk];
            float p3 = KtP[(rbase + 3) * QP + kk];
            float4 v4 = *(const float4*)&Vs[kk * QP + cbase];
            o_[0][0] += p0 * v4.x; o_[0][1] += p0 * v4.y; o_[0][2] += p0 * v4.z; o_[0][3] += p0 * v4.w;
            o_[1][0] += p1 * v4.x; o_[1][1] += p1 * v4.y; o_[1][2] += p1 * v4.z; o_[1][3] += p1 * v4.w;
            o_[2][0] += p2 * v4.x; o_[2][1] += p2 * v4.y; o_[2][2] += p2 * v4.z; o_[2][3] += p2 * v4.w;
            o_[3][0] += p3 * v4.x; o_[3][1] += p3 * v4.y; o_[3][2] += p3 * v4.z; o_[3][3] += p3 * v4.w;
        }
    }

#pragma unroll
    for (int i = 0; i < 4; i++) {
        float invl = 1.f / l_[i];
        int q = q0 + rbase + i;
        size_t base = ((size_t)(b * TSEQ + q)) * DMODEL + h * DHEAD + cbase;
#pragma unroll
        for (int j = 0; j < 4; j++)
            split_store(o_[i][j] * invl, &Oh[base + j], &Ol[base + j]);
    }
}

// =================================================================
// LayerNorm; optionally also emits bf16 hi/lo of the output.
// =================================================================
__global__ __launch_bounds__(256)
void ln_kernel(const float* __restrict__ in, const float* __restrict__ g,
               const float* __restrict__ be, float* __restrict__ out,
               __nv_bfloat16* __restrict__ Oh, __nv_bfloat16* __restrict__ Ol)
{
    const int row = blockIdx.x;
    const int tid = threadIdx.x;
    const float* xr = in + (size_t)row * DMODEL;

    float v0 = xr[tid], v1 = xr[tid + 256], v2 = xr[tid + 512];
    float s = v0 + v1 + v2;
    float s2 = v0 * v0 + v1 * v1 + v2 * v2;

    __shared__ float rs[8], rs2[8], stats[2];
#pragma unroll
    for (int off = 16; off; off >>= 1) {
        s  += __shfl_xor_sync(0xffffffffu, s,  off);
        s2 += __shfl_xor_sync(0xffffffffu, s2, off);
    }
    int w = tid >> 5, lane = tid & 31;
    if (lane == 0) { rs[w] = s; rs2[w] = s2; }
    __syncthreads();
    if (tid == 0) {
        float S = 0.f, S2 = 0.f;
#pragma unroll
        for (int i = 0; i < 8; i++) { S += rs[i]; S2 += rs2[i]; }
        float mean = S * (1.f / DMODEL);
        float var  = S2 * (1.f / DMODEL) - mean * mean;
        stats[0] = mean;
        stats[1] = rsqrtf(var + 1e-5f);
    }
    __syncthreads();
    float mean = stats[0], r = stats[1];
    size_t rb = (size_t)row * DMODEL;
    float vv[3] = {v0, v1, v2};
#pragma unroll
    for (int p = 0; p < 3; p++) {
        int c = tid + p * 256;
        float y = (vv[p] - mean) * r * g[c] + be[c];
        out[rb + c] = y;
        if (Oh) split_store(y, &Oh[rb + c], &Ol[rb + c]);
    }
}

// =================================================================
// Host launch
// =================================================================
extern "C" void kernel_launch(void* const* d_in, const int* in_sizes, int n_in,
                              void* d_out, int out_size)
{
    const float* x  = (const float*)d_in[0];
    const float* wq = (const float*)d_in[1];
    const float* bq = (const float*)d_in[2];
    const float* wk = (const float*)d_in[3];
    const float* bk = (const float*)d_in[4];
    const float* wv = (const float*)d_in[5];
    const float* bv = (const float*)d_in[6];
    const float* wo = (const float*)d_in[7];
    const float* bo = (const float*)d_in[8];
    const float* w1 = (const float*)d_in[9];
    const float* b1 = (const float*)d_in[10];
    const float* w2 = (const float*)d_in[11];
    const float* b2 = (const float*)d_in[12];
    const float* g1 = (const float*)d_in[13];
    const float* be1= (const float*)d_in[14];
    const float* g2 = (const float*)d_in[15];
    const float* be2= (const float*)d_in[16];
    float* out = (float*)d_out;

    float *Q, *K, *V, *R1, *H, *R2;
    __nv_bfloat16 *Ah, *Al, *FFh, *FFl, *Bh, *Bl;
    cudaGetSymbolAddress((void**)&Q,   g_Q);
    cudaGetSymbolAddress((void**)&K,   g_K);
    cudaGetSymbolAddress((void**)&V,   g_V);
    cudaGetSymbolAddress((void**)&R1,  g_R1);
    cudaGetSymbolAddress((void**)&H,   g_H);
    cudaGetSymbolAddress((void**)&R2,  g_R2);
    cudaGetSymbolAddress((void**)&Ah,  g_ahi);
    cudaGetSymbolAddress((void**)&Al,  g_alo);
    cudaGetSymbolAddress((void**)&FFh, g_ffhi);
    cudaGetSymbolAddress((void**)&FFl, g_fflo);
    cudaGetSymbolAddress((void**)&Bh,  g_bhi);
    cudaGetSymbolAddress((void**)&Bl,  g_blo);

    cudaFuncSetAttribute(attn_kernel, cudaFuncAttributeMaxDynamicSharedMemorySize, ATT_SMEM);
    cudaFuncSetAttribute(gemm_mma, cudaFuncAttributeMaxDynamicSharedMemorySize, GEMM_SMEM);

    // weight transpose + hi/lo split
    dim3 tb(32, 8);
    const float*  wsrc[6] = {wq, wk, wv, wo, w1, w2};
    const size_t  offs[6] = {WQ_OFF, WK_OFF, WV_OFF, WO_OFF, W1_OFF, W2_OFF};
    const int     wkd[6]  = {768, 768, 768, 768, 768, 3072};
    const int     wnd[6]  = {768, 768, 768, 768, 3072, 768};
    for (int i = 0; i < 6; i++)
        wsplit_kernel<<<dim3(wkd[i] / 32, wnd[i] / 32), tb>>>(
            wsrc[i], Bh + offs[i], Bl + offs[i], wkd[i], wnd[i]);

    // x -> bf16 hi/lo
    asplit_kernel<<<MTOK * DMODEL / 1024, 256>>>(x, Ah, Al);

    dim3 gD(DMODEL / 128, MTOK / 128);  // (6, 64)
    dim3 gF(DFF / 128,    MTOK / 128);  // (24, 64)

    // QKV projections
    gemm_mma<<<gD, 256, GEMM_SMEM>>>(Ah, Al, Bh + WQ_OFF, Bl + WQ_OFF, bq, nullptr, Q, nullptr, nullptr, DMODEL, DMODEL, 0);
    gemm_mma<<<gD, 256, GEMM_SMEM>>>(Ah, Al, Bh + WK_OFF, Bl + WK_OFF, bk, nullptr, K, nullptr, nullptr, DMODEL, DMODEL, 0);
    gemm_mma<<<gD, 256, GEMM_SMEM>>>(Ah, Al, Bh + WV_OFF, Bl + WV_OFF, bv, nullptr, V, nullptr, nullptr, DMODEL, DMODEL, 0);

    // causal flash attention -> ATT hi/lo into Ah/Al (x itself untouched)
    attn_kernel<<<dim3(TSEQ / 64, NHEADS, BBATCH), 256, ATT_SMEM>>>(Q, K, V, Ah, Al);

    // output projection + residual(x), LN1 (emits H hi/lo into Ah/Al)
    gemm_mma<<<gD, 256, GEMM_SMEM>>>(Ah, Al, Bh + WO_OFF, Bl + WO_OFF, bo, x, R1, nullptr, nullptr, DMODEL, DMODEL, 0);
    ln_kernel<<<MTOK, 256>>>(R1, g1, be1, H, Ah, Al);

    // FFN: W1 (+relu) -> FF hi/lo only; W2 + residual(H)
    gemm_mma<<<gF, 256, GEMM_SMEM>>>(Ah, Al, Bh + W1_OFF, Bl + W1_OFF, b1, nullptr, nullptr, FFh, FFl, DFF, DMODEL, 1);
    gemm_mma<<<gD, 256, GEMM_SMEM>>>(FFh, FFl, Bh + W2_OFF, Bl + W2_OFF, b2, H, R2, nullptr, nullptr, DMODEL, DFF, 0);

    // LN2 -> output
    ln_kernel<<<MTOK, 256>>>(R2, g2, be2, out, nullptr, nullptr);
}

// round 12
// speedup vs baseline: 2.7219x; 1.6450x over previous
#include <cuda_runtime.h>
#include <cuda_bf16.h>
#include <stdint.h>
#include <math.h>

// ---------------- problem constants ----------------
#define DMODEL 768
#define NHEADS 12
#define DHEAD  64
#define DFF    3072
#define BBATCH 2
#define TSEQ   4096
#define MTOK   (BBATCH * TSEQ)   // 8192 tokens

// weight (transposed [N,K], bf16 hi/lo) offsets inside g_bhi/g_blo
#define WQ_OFF 0
#define WK_OFF (768*768)
#define WV_OFF (2*768*768)
#define WV_END (3*768*768)
#define WO_OFF (3*768*768)
#define W1_OFF (4*768*768)                 // [3072][768]
#define W2_OFF (4*768*768 + 768*3072)      // [768][3072]
#define WTOT   (4*768*768 + 2*768*3072)

// ---------------- scratch (device globals; no allocation allowed) ----------------
__device__ float g_R1 [MTOK * DMODEL];
__device__ float g_H  [MTOK * DMODEL];
__device__ float g_R2 [MTOK * DMODEL];
__device__ __nv_bfloat16 g_qhi[MTOK * DMODEL];
__device__ __nv_bfloat16 g_qlo[MTOK * DMODEL];
__device__ __nv_bfloat16 g_khi[MTOK * DMODEL];
__device__ __nv_bfloat16 g_klo[MTOK * DMODEL];
__device__ __nv_bfloat16 g_vhi[MTOK * DMODEL];
__device__ __nv_bfloat16 g_vlo[MTOK * DMODEL];
__device__ __nv_bfloat16 g_ahi [MTOK * DMODEL];
__device__ __nv_bfloat16 g_alo [MTOK * DMODEL];
__device__ __nv_bfloat16 g_ffhi[MTOK * DFF];
__device__ __nv_bfloat16 g_fflo[MTOK * DFF];
__device__ __nv_bfloat16 g_bhi [WTOT];
__device__ __nv_bfloat16 g_blo [WTOT];

// ---------------- helpers ----------------
__device__ __forceinline__ uint32_t smem_u32(const void* p) {
    uint32_t a;
    asm("{ .reg .u64 t; cvta.to.shared.u64 t, %1; cvt.u32.u64 %0, t; }" : "=r"(a) : "l"(p));
    return a;
}
__device__ __forceinline__ void cp16(uint32_t d, const void* s) {
    asm volatile("cp.async.cg.shared.global [%0], [%1], 16;" :: "r"(d), "l"(s));
}
#define CP_COMMIT() asm volatile("cp.async.commit_group;" ::: "memory")
#define CP_WAIT0()  asm volatile("cp.async.wait_group 0;"  ::: "memory")
#define CP_WAIT1()  asm volatile("cp.async.wait_group 1;"  ::: "memory")

#define LDSM4(r0, r1, r2, r3, addr) \
    asm volatile("ldmatrix.sync.aligned.m8n8.x4.shared.b16 {%0,%1,%2,%3}, [%4];" \
        : "=r"(r0), "=r"(r1), "=r"(r2), "=r"(r3) : "r"(addr))
#define LDSM4T(r0, r1, r2, r3, addr) \
    asm volatile("ldmatrix.sync.aligned.m8n8.x4.trans.shared.b16 {%0,%1,%2,%3}, [%4];" \
        : "=r"(r0), "=r"(r1), "=r"(r2), "=r"(r3) : "r"(addr))

#define MMA16816(c, a, b) \
    asm volatile("mma.sync.aligned.m16n8k16.row.col.f32.bf16.bf16.f32 " \
        "{%0,%1,%2,%3},{%4,%5,%6,%7},{%8,%9},{%0,%1,%2,%3};" \
        : "+f"((c)[0]), "+f"((c)[1]), "+f"((c)[2]), "+f"((c)[3]) \
        : "r"((a)[0]), "r"((a)[1]), "r"((a)[2]), "r"((a)[3]), \
          "r"((b)[0]), "r"((b)[1]))

__device__ __forceinline__ void split_store(float v, __nv_bfloat16* hi, __nv_bfloat16* lo) {
    __nv_bfloat16 h = __float2bfloat16(v);
    *hi = h;
    *lo = __float2bfloat16(v - __bfloat162float(h));
}
// pack two fp32 into bf16x2 hi and residual lo
__device__ __forceinline__ void split2(float a, float b, uint32_t& hi, uint32_t& lo) {
    __nv_bfloat162 hp, lp;
    hp.x = __float2bfloat16(a); hp.y = __float2bfloat16(b);
    lp.x = __float2bfloat16(a - __bfloat162float(hp.x));
    lp.y = __float2bfloat16(b - __bfloat162float(hp.y));
    hi = *(uint32_t*)&hp; lo = *(uint32_t*)&lp;
}

// =================================================================
// mma.sync GEMM: C[M,N] = A[M,K] @ Bt[N,K]^T (+bias)(+res)(+relu)
// (unchanged from R10 — validated)
// =================================================================
#define BKG   32
#define ROWB  80
#define TILEB 10240
#define STAGEB (4 * TILEB)
#define GEMM_SMEM (2 * STAGEB)

__device__ __forceinline__ void load_stage(
    uint32_t st, const __nv_bfloat16* Ah, const __nv_bfloat16* Al,
    const __nv_bfloat16* Bh, const __nv_bfloat16* Bl,
    int bm, int bn, int k0, int K, int tid)
{
#pragma unroll
    for (int i = 0; i < 2; i++) {
        int c = tid + i * 256;
        int r = c >> 2;
        int kc = (c & 3) * 8;
        uint32_t so = (uint32_t)(r * ROWB + kc * 2);
        size_t goA = (size_t)(bm + r) * K + k0 + kc;
        size_t goB = (size_t)(bn + r) * K + k0 + kc;
        cp16(st + so,             Ah + goA);
        cp16(st + TILEB + so,     Al + goA);
        cp16(st + 2 * TILEB + so, Bh + goB);
        cp16(st + 3 * TILEB + so, Bl + goB);
    }
}

__global__ __launch_bounds__(256, 1)
void gemm_mma(const __nv_bfloat16* __restrict__ Ah, const __nv_bfloat16* __restrict__ Al,
              const __nv_bfloat16* __restrict__ Bh, const __nv_bfloat16* __restrict__ Bl,
              const float* __restrict__ bias, const float* __restrict__ res,
              float* __restrict__ C, __nv_bfloat16* __restrict__ Chi,
              __nv_bfloat16* __restrict__ Clo, int N, int K, int relu)
{
    extern __shared__ char smem[];
    const uint32_t sb = smem_u32(smem);
    const int tid = threadIdx.x;
    const int wid = tid >> 5, lane = tid & 31;
    const int wm = wid & 1;
    const int wn = wid >> 1;
    const int bm = blockIdx.y * 128, bn = blockIdx.x * 128;

    float acc[4][4][4];
#pragma unroll
    for (int mt = 0; mt < 4; mt++)
#pragma unroll
        for (int nt = 0; nt < 4; nt++)
#pragma unroll
            for (int i = 0; i < 4; i++) acc[mt][nt][i] = 0.f;

    const int nk = K / BKG;
    load_stage(sb, Ah, Al, Bh, Bl, bm, bn, 0, K, tid);
    CP_COMMIT();

    for (int ks = 0; ks < nk; ks++) {
        if (ks + 1 < nk) {
            load_stage(sb + ((ks + 1) & 1) * STAGEB, Ah, Al, Bh, Bl,
                       bm, bn, (ks + 1) * BKG, K, tid);
            CP_COMMIT();
            CP_WAIT1();
        } else {
            CP_WAIT0();
        }
        __syncthreads();

        const uint32_t st = sb + (ks & 1) * STAGEB;
#pragma unroll
        for (int kk = 0; kk < 2; kk++) {
            uint32_t ah[4][4], al[4][4];
            uint32_t aoff = st + (uint32_t)((wm * 64 + (lane & 15)) * ROWB)
                          + kk * 32 + ((lane >> 4) & 1) * 16;
#pragma unroll
            for (int mt = 0; mt < 4; mt++) {
                LDSM4(ah[mt][0], ah[mt][1], ah[mt][2], ah[mt][3], aoff + mt * 16 * ROWB);
                LDSM4(al[mt][0], al[mt][1], al[mt][2], al[mt][3], aoff + TILEB + mt * 16 * ROWB);
            }
            uint32_t bh[4][2], bl[4][2];
            uint32_t boff = st + 2 * TILEB
                          + (uint32_t)((wn * 32 + (lane & 7) + ((lane >> 4) & 1) * 8) * ROWB)
                          + kk * 32 + ((lane >> 3) & 1) * 16;
#pragma unroll
            for (int np = 0; np < 2; np++) {
                uint32_t r0, r1, r2, r3;
                LDSM4(r0, r1, r2, r3, boff + np * 16 * ROWB);
                bh[2*np][0] = r0; bh[2*np][1] = r1; bh[2*np+1][0] = r2; bh[2*np+1][1] = r3;
                LDSM4(r0, r1, r2, r3, boff + TILEB + np * 16 * ROWB);
                bl[2*np][0] = r0; bl[2*np][1] = r1; bl[2*np+1][0] = r2; bl[2*np+1][1] = r3;
            }
#pragma unroll
            for (int mt = 0; mt < 4; mt++)
#pragma unroll
                for (int nt = 0; nt < 4; nt++) {
                    MMA16816(acc[mt][nt], ah[mt], bh[nt]);
                    MMA16816(acc[mt][nt], ah[mt], bl[nt]);
                    MMA16816(acc[mt][nt], al[mt], bh[nt]);
                }
        }
        __syncthreads();
    }

#pragma unroll
    for (int mt = 0; mt < 4; mt++)
#pragma unroll
        for (int nt = 0; nt < 4; nt++) {
            int row = bm + wm * 64 + mt * 16 + (lane >> 2);
            int col = bn + wn * 32 + nt * 8 + (lane & 3) * 2;
            float b0 = bias[col], b1 = bias[col + 1];
#pragma unroll
            for (int half = 0; half < 2; half++) {
                int r = row + half * 8;
                size_t idx = (size_t)r * N + col;
                float v0 = acc[mt][nt][half * 2 + 0] + b0;
                float v1 = acc[mt][nt][half * 2 + 1] + b1;
                if (res) {
                    float2 rv = *(const float2*)&res[idx];
                    v0 += rv.x; v1 += rv.y;
                }
                if (relu) { v0 = fmaxf(v0, 0.f); v1 = fmaxf(v1, 0.f); }
                if (C) { float2 o = make_float2(v0, v1); *(float2*)&C[idx] = o; }
                if (Chi) {
                    uint32_t hi, lo;
                    split2(v0, v1, hi, lo);
                    *(uint32_t*)&Chi[idx] = hi;
                    *(uint32_t*)&Clo[idx] = lo;
                }
            }
        }
}

// =================================================================
// Weight transpose + split, activation split (unchanged)
// =================================================================
__global__ void wsplit_kernel(const float* __restrict__ W, __nv_bfloat16* __restrict__ Th,
                              __nv_bfloat16* __restrict__ Tl, int Kd, int Nd)
{
    __shared__ float t[32][33];
    int k0 = blockIdx.x * 32, n0 = blockIdx.y * 32;
    int tx = threadIdx.x, ty = threadIdx.y;
    for (int i = ty; i < 32; i += 8)
        t[i][tx] = W[(size_t)(k0 + i) * Nd + n0 + tx];
    __syncthreads();
    for (int i = ty; i < 32; i += 8) {
        float v = t[tx][i];
        size_t o = (size_t)(n0 + i) * Kd + k0 + tx;
        split_store(v, &Th[o], &Tl[o]);
    }
}

__global__ void asplit_kernel(const float* __restrict__ A, __nv_bfloat16* __restrict__ Ah,
                              __nv_bfloat16* __restrict__ Al)
{
    int i = (blockIdx.x * blockDim.x + threadIdx.x) * 4;
    float4 v = *(const float4*)&A[i];
    split_store(v.x, &Ah[i + 0], &Al[i + 0]);
    split_store(v.y, &Ah[i + 1], &Al[i + 1]);
    split_store(v.z, &Ah[i + 2], &Al[i + 2]);
    split_store(v.w, &Ah[i + 3], &Al[i + 3]);
}

// =================================================================
// Flash attention (causal) on mma.sync, bf16 hi/lo 3-term.
// Block: 128 queries x (head, batch). 8 warps; warp w owns rows w*16..+15.
// Key chunks of 64, double-buffered cp.async.
// Q/K/V smem rows: 64 bf16 data padded to pitch 72 (144 B).
// =================================================================
#define APITCH   144                 // bytes per smem row
#define AQH_OFF  0
#define AQL_OFF  18432               // 128*144
#define AST_OFF  36864               // start of K/V stages
#define AST_SZ   36864               // 4 tiles * 64*144
#define AKH 0
#define AKL 9216
#define AVH 18432
#define AVL 27648
#define ATT_SMEM (AST_OFF + 2 * AST_SZ)   // 110592 B

__device__ __forceinline__ void att_load_kv(
    uint32_t stbase, const __nv_bfloat16* Kh, const __nv_bfloat16* Kl,
    const __nv_bfloat16* Vh, const __nv_bfloat16* Vl,
    int b, int h, int j0, int tid)
{
#pragma unroll
    for (int i = 0; i < 8; i++) {
        int idx = tid + i * 256;          // 0..2047
        int t   = idx >> 9;               // which tile: 0=Kh 1=Kl 2=Vh 3=Vl
        int rem = idx & 511;
        int r   = rem >> 3;               // row 0..63
        int c   = (rem & 7) * 8;          // elem offset
        size_t go = (size_t)(b * TSEQ + j0 + r) * DMODEL + h * DHEAD + c;
        const __nv_bfloat16* src = (t == 0) ? Kh : (t == 1) ? Kl : (t == 2) ? Vh : Vl;
        cp16(stbase + t * 9216 + r * APITCH + c * 2, src + go);
    }
}

__global__ __launch_bounds__(256, 1)
void attn_mma(const __nv_bfloat16* __restrict__ Qh, const __nv_bfloat16* __restrict__ Ql,
              const __nv_bfloat16* __restrict__ Kh, const __nv_bfloat16* __restrict__ Kl,
              const __nv_bfloat16* __restrict__ Vh, const __nv_bfloat16* __restrict__ Vl,
              __nv_bfloat16* __restrict__ Oh, __nv_bfloat16* __restrict__ Ol)
{
    extern __shared__ char smem[];
    const uint32_t sb = smem_u32(smem);
    const int tid = threadIdx.x;
    const int wid = tid >> 5, lane = tid & 31;
    const int q0 = (gridDim.x - 1 - blockIdx.x) * 128;   // long blocks first
    const int h  = blockIdx.y;
    const int b  = blockIdx.z;

    // ---- load Q tile (hi+lo): 2048 cp16, 8 per thread ----
#pragma unroll
    for (int i = 0; i < 8; i++) {
        int idx = tid + i * 256;          // 0..2047
        int hl  = idx >> 10;              // 0=hi 1=lo
        int rem = idx & 1023;
        int r   = rem >> 3;               // 0..127
        int c   = (rem & 7) * 8;
        size_t go = (size_t)(b * TSEQ + q0 + r) * DMODEL + h * DHEAD + c;
        cp16(sb + hl * 18432 + r * APITCH + c * 2, (hl ? Ql : Qh) + go);
    }
    CP_COMMIT();

    const int nch = q0 / 64 + 2;
    att_load_kv(sb + AST_OFF, Kh, Kl, Vh, Vl, b, h, 0, tid);
    CP_COMMIT();

    float m2[2] = {-1e30f, -1e30f};
    float l2[2] = {0.f, 0.f};
    float o[8][4];
#pragma unroll
    for (int nt = 0; nt < 8; nt++)
#pragma unroll
        for (int i = 0; i < 4; i++) o[nt][i] = 0.f;

    const int r0g = q0 + wid * 16 + (lane >> 2);     // global query row (half 0)

    for (int ci = 0; ci < nch; ci++) {
        __syncthreads();    // all warps done with the stage we are about to overwrite
        if (ci + 1 < nch) {
            att_load_kv(sb + AST_OFF + ((ci + 1) & 1) * AST_SZ,
                        Kh, Kl, Vh, Vl, b, h, (ci + 1) * 64, tid);
            CP_COMMIT();
            CP_WAIT1();
        } else {
            CP_WAIT0();
        }
        __syncthreads();    // current stage data visible to all

        const uint32_t st = sb + AST_OFF + (ci & 1) * AST_SZ;
        const int j0 = ci * 64;

        // ---- S = Q K^T (3-term), fp32 accum ----
        float s[8][4];
#pragma unroll
        for (int nt = 0; nt < 8; nt++)
#pragma unroll
            for (int i = 0; i < 4; i++) s[nt][i] = 0.f;

#pragma unroll
        for (int kk = 0; kk < 4; kk++) {
            uint32_t qa[4], qb[4];
            uint32_t aoff = sb + (uint32_t)((wid * 16 + (lane & 15)) * APITCH)
                          + kk * 32 + ((lane >> 4) & 1) * 16;
            LDSM4(qa[0], qa[1], qa[2], qa[3], aoff);
            LDSM4(qb[0], qb[1], qb[2], qb[3], aoff + AQL_OFF);
#pragma unroll
            for (int np = 0; np < 4; np++) {
                uint32_t boff = st + AKH
                              + (uint32_t)((np * 16 + (lane & 7) + ((lane >> 4) & 1) * 8) * APITCH)
                              + kk * 32 + ((lane >> 3) & 1) * 16;
                uint32_t k0r, k1r, k2r, k3r;
                LDSM4(k0r, k1r, k2r, k3r, boff);
                uint32_t l0r, l1r, l2r, l3r;
                LDSM4(l0r, l1r, l2r, l3r, boff + (AKL - AKH));
                uint32_t bh0[2] = {k0r, k1r}, bh1[2] = {k2r, k3r};
                uint32_t bl0[2] = {l0r, l1r}, bl1[2] = {l2r, l3r};
                MMA16816(s[2*np],   qa, bh0);
                MMA16816(s[2*np],   qa, bl0);
                MMA16816(s[2*np],   qb, bh0);
                MMA16816(s[2*np+1], qa, bh1);
                MMA16816(s[2*np+1], qa, bl1);
                MMA16816(s[2*np+1], qb, bh1);
            }
        }

        // ---- scale + causal mask ----
#pragma unroll
        for (int nt = 0; nt < 8; nt++)
#pragma unroll
            for (int i = 0; i < 4; i++) s[nt][i] *= 0.125f;

        if (j0 >= q0) {
#pragma unroll
            for (int nt = 0; nt < 8; nt++) {
                int col = j0 + nt * 8 + (lane & 3) * 2;
                if (col     > r0g)     s[nt][0] = -1e30f;
                if (col + 1 > r0g)     s[nt][1] = -1e30f;
                if (col     > r0g + 8) s[nt][2] = -1e30f;
                if (col + 1 > r0g + 8) s[nt][3] = -1e30f;
            }
        }

        // ---- streaming softmax (per row-half; quad lanes share a row) ----
#pragma unroll
        for (int rh = 0; rh < 2; rh++) {
            float cm = -1e30f;
#pragma unroll
            for (int nt = 0; nt < 8; nt++)
                cm = fmaxf(cm, fmaxf(s[nt][rh*2], s[nt][rh*2+1]));
            cm = fmaxf(cm, __shfl_xor_sync(0xffffffffu, cm, 1));
            cm = fmaxf(cm, __shfl_xor_sync(0xffffffffu, cm, 2));
            float mn = fmaxf(m2[rh], cm);
            float corr = __expf(m2[rh] - mn);
            m2[rh] = mn;
            float rs = 0.f;
#pragma unroll
            for (int nt = 0; nt < 8; nt++) {
                float p0 = __expf(s[nt][rh*2]   - mn);
                float p1 = __expf(s[nt][rh*2+1] - mn);
                s[nt][rh*2] = p0; s[nt][rh*2+1] = p1;
                rs += p0 + p1;
            }
            rs += __shfl_xor_sync(0xffffffffu, rs, 1);
            rs += __shfl_xor_sync(0xffffffffu, rs, 2);
            l2[rh] = l2[rh] * corr + rs;
#pragma unroll
            for (int nt = 0; nt < 8; nt++) {
                o[nt][rh*2]   *= corr;
                o[nt][rh*2+1] *= corr;
            }
        }

        // ---- O += P V (3-term); P fragments built from s in registers ----
#pragma unroll
        for (int kc = 0; kc < 4; kc++) {
            uint32_t ph[4], pl[4];
            split2(s[2*kc][0],   s[2*kc][1],   ph[0], pl[0]);
            split2(s[2*kc][2],   s[2*kc][3],   ph[1], pl[1]);
            split2(s[2*kc+1][0], s[2*kc+1][1], ph[2], pl[2]);
            split2(s[2*kc+1][2], s[2*kc+1][3], ph[3], pl[3]);
#pragma unroll
            for (int np = 0; np < 4; np++) {
                uint32_t voff = st + AVH
                              + (uint32_t)((kc * 16 + (lane & 15)) * APITCH)
                              + (np * 16 + ((lane >> 4) & 1) * 8) * 2;
                uint32_t v0r, v1r, v2r, v3r;
                LDSM4T(v0r, v1r, v2r, v3r, voff);
                uint32_t w0r, w1r, w2r, w3r;
                LDSM4T(w0r, w1r, w2r, w3r, voff + (AVL - AVH));
                uint32_t vh0[2] = {v0r, v1r}, vh1[2] = {v2r, v3r};
                uint32_t vl0[2] = {w0r, w1r}, vl1[2] = {w2r, w3r};
                MMA16816(o[2*np],   ph, vh0);
                MMA16816(o[2*np],   ph, vl0);
                MMA16816(o[2*np],   pl, vh0);
                MMA16816(o[2*np+1], ph, vh1);
                MMA16816(o[2*np+1], ph, vl1);
                MMA16816(o[2*np+1], pl, vh1);
            }
        }
    }

    // ---- normalize + write bf16 hi/lo ----
    float inv0 = 1.f / l2[0], inv1 = 1.f / l2[1];
#pragma unroll
    for (int nt = 0; nt < 8; nt++) {
        int col = h * DHEAD + nt * 8 + (lane & 3) * 2;
        size_t i0 = (size_t)(b * TSEQ + r0g) * DMODEL + col;
        size_t i1 = (size_t)(b * TSEQ + r0g + 8) * DMODEL + col;
        uint32_t hi, lo;
        split2(o[nt][0] * inv0, o[nt][1] * inv0, hi, lo);
        *(uint32_t*)&Oh[i0] = hi; *(uint32_t*)&Ol[i0] = lo;
        split2(o[nt][2] * inv1, o[nt][3] * inv1, hi, lo);
        *(uint32_t*)&Oh[i1] = hi; *(uint32_t*)&Ol[i1] = lo;
    }
}

// =================================================================
// LayerNorm; optionally also emits bf16 hi/lo of the output.
// =================================================================
__global__ __launch_bounds__(256)
void ln_kernel(const float* __restrict__ in, const float* __restrict__ g,
               const float* __restrict__ be, float* __restrict__ out,
               __nv_bfloat16* __restrict__ Oh, __nv_bfloat16* __restrict__ Ol)
{
    const int row = blockIdx.x;
    const int tid = threadIdx.x;
    const float* xr = in + (size_t)row * DMODEL;

    float v0 = xr[tid], v1 = xr[tid + 256], v2 = xr[tid + 512];
    float s = v0 + v1 + v2;
    float s2 = v0 * v0 + v1 * v1 + v2 * v2;

    __shared__ float rs[8], rs2[8], stats[2];
#pragma unroll
    for (int off = 16; off; off >>= 1) {
        s  += __shfl_xor_sync(0xffffffffu, s,  off);
        s2 += __shfl_xor_sync(0xffffffffu, s2, off);
    }
    int w = tid >> 5, lane = tid & 31;
    if (lane == 0) { rs[w] = s; rs2[w] = s2; }
    __syncthreads();
    if (tid == 0) {
        float S = 0.f, S2 = 0.f;
#pragma unroll
        for (int i = 0; i < 8; i++) { S += rs[i]; S2 += rs2[i]; }
        float mean = S * (1.f / DMODEL);
        float var  = S2 * (1.f / DMODEL) - mean * mean;
        stats[0] = mean;
        stats[1] = rsqrtf(var + 1e-5f);
    }
    __syncthreads();
    float mean = stats[0], r = stats[1];
    size_t rb = (size_t)row * DMODEL;
    float vv[3] = {v0, v1, v2};
#pragma unroll
    for (int p = 0; p < 3; p++) {
        int c = tid + p * 256;
        float y = (vv[p] - mean) * r * g[c] + be[c];
        out[rb + c] = y;
        if (Oh) split_store(y, &Oh[rb + c], &Ol[rb + c]);
    }
}

// =================================================================
// Host launch
// =================================================================
extern "C" void kernel_launch(void* const* d_in, const int* in_sizes, int n_in,
                              void* d_out, int out_size)
{
    const float* x  = (const float*)d_in[0];
    const float* wq = (const float*)d_in[1];
    const float* bq = (const float*)d_in[2];
    const float* wk = (const float*)d_in[3];
    const float* bk = (const float*)d_in[4];
    const float* wv = (const float*)d_in[5];
    const float* bv = (const float*)d_in[6];
    const float* wo = (const float*)d_in[7];
    const float* bo = (const float*)d_in[8];
    const float* w1 = (const float*)d_in[9];
    const float* b1 = (const float*)d_in[10];
    const float* w2 = (const float*)d_in[11];
    const float* b2 = (const float*)d_in[12];
    const float* g1 = (const float*)d_in[13];
    const float* be1= (const float*)d_in[14];
    const float* g2 = (const float*)d_in[15];
    const float* be2= (const float*)d_in[16];
    float* out = (float*)d_out;

    float *R1, *H, *R2;
    __nv_bfloat16 *Qh, *Ql, *Kh, *Kl, *Vh, *Vl, *Ah, *Al, *FFh, *FFl, *Bh, *Bl;
    cudaGetSymbolAddress((void**)&R1,  g_R1);
    cudaGetSymbolAddress((void**)&H,   g_H);
    cudaGetSymbolAddress((void**)&R2,  g_R2);
    cudaGetSymbolAddress((void**)&Qh,  g_qhi);
    cudaGetSymbolAddress((void**)&Ql,  g_qlo);
    cudaGetSymbolAddress((void**)&Kh,  g_khi);
    cudaGetSymbolAddress((void**)&Kl,  g_klo);
    cudaGetSymbolAddress((void**)&Vh,  g_vhi);
    cudaGetSymbolAddress((void**)&Vl,  g_vlo);
    cudaGetSymbolAddress((void**)&Ah,  g_ahi);
    cudaGetSymbolAddress((void**)&Al,  g_alo);
    cudaGetSymbolAddress((void**)&FFh, g_ffhi);
    cudaGetSymbolAddress((void**)&FFl, g_fflo);
    cudaGetSymbolAddress((void**)&Bh,  g_bhi);
    cudaGetSymbolAddress((void**)&Bl,  g_blo);

    cudaFuncSetAttribute(attn_mma, cudaFuncAttributeMaxDynamicSharedMemorySize, ATT_SMEM);
    cudaFuncSetAttribute(gemm_mma, cudaFuncAttributeMaxDynamicSharedMemorySize, GEMM_SMEM);

    // weight transpose + hi/lo split
    dim3 tb(32, 8);
    const float*  wsrc[6] = {wq, wk, wv, wo, w1, w2};
    const size_t  offs[6] = {WQ_OFF, WK_OFF, WV_OFF, WO_OFF, W1_OFF, W2_OFF};
    const int     wkd[6]  = {768, 768, 768, 768, 768, 3072};
    const int     wnd[6]  = {768, 768, 768, 768, 3072, 768};
    for (int i = 0; i < 6; i++)
        wsplit_kernel<<<dim3(wkd[i] / 32, wnd[i] / 32), tb>>>(
            wsrc[i], Bh + offs[i], Bl + offs[i], wkd[i], wnd[i]);

    // x -> bf16 hi/lo (into Ah/Al)
    asplit_kernel<<<MTOK * DMODEL / 1024, 256>>>(x, Ah, Al);

    dim3 gD(DMODEL / 128, MTOK / 128);  // (6, 64)
    dim3 gF(DFF / 128,    MTOK / 128);  // (24, 64)

    // QKV projections -> bf16 hi/lo directly (no fp32 QKV)
    gemm_mma<<<gD, 256, GEMM_SMEM>>>(Ah, Al, Bh + WQ_OFF, Bl + WQ_OFF, bq, nullptr, nullptr, Qh, Ql, DMODEL, DMODEL, 0);
    gemm_mma<<<gD, 256, GEMM_SMEM>>>(Ah, Al, Bh + WK_OFF, Bl + WK_OFF, bk, nullptr, nullptr, Kh, Kl, DMODEL, DMODEL, 0);
    gemm_mma<<<gD, 256, GEMM_SMEM>>>(Ah, Al, Bh + WV_OFF, Bl + WV_OFF, bv, nullptr, nullptr, Vh, Vl, DMODEL, DMODEL, 0);

    // causal flash attention on tensor cores -> ATT hi/lo into Ah/Al
    attn_mma<<<dim3(TSEQ / 128, NHEADS, BBATCH), 256, ATT_SMEM>>>(Qh, Ql, Kh, Kl, Vh, Vl, Ah, Al);

    // output projection + residual(x), LN1 (emits H hi/lo into Ah/Al)
    gemm_mma<<<gD, 256, GEMM_SMEM>>>(Ah, Al, Bh + WO_OFF, Bl + WO_OFF, bo, x, R1, nullptr, nullptr, DMODEL, DMODEL, 0);
    ln_kernel<<<MTOK, 256>>>(R1, g1, be1, H, Ah, Al);

    // FFN: W1 (+relu) -> FF hi/lo only; W2 + residual(H)
    gemm_mma<<<gF, 256, GEMM_SMEM>>>(Ah, Al, Bh + W1_OFF, Bl + W1_OFF, b1, nullptr, nullptr, FFh, FFl, DFF, DMODEL, 1);
    gemm_mma<<<gD, 256, GEMM_SMEM>>>(FFh, FFl, Bh + W2_OFF, Bl + W2_OFF, b2, H, R2, nullptr, nullptr, DMODEL, DFF, 0);

    // LN2 -> output
    ln_kernel<<<MTOK, 256>>>(R2, g2, be2, out, nullptr, nullptr);
}

// round 13
// speedup vs baseline: 3.6558x; 1.3431x over previous
#include <cuda_runtime.h>
#include <cuda_fp16.h>
#include <stdint.h>
#include <math.h>

// ---------------- problem constants ----------------
#define DMODEL 768
#define NHEADS 12
#define DHEAD  64
#define DFF    3072
#define BBATCH 2
#define TSEQ   4096
#define MTOK   (BBATCH * TSEQ)   // 8192 tokens

// weight (transposed [N,K], fp16 hi/lo) offsets inside g_bhi/g_blo
#define WQ_OFF 0
#define WK_OFF (768*768)
#define WV_OFF (2*768*768)
#define WO_OFF (3*768*768)
#define W1_OFF (4*768*768)                 // [3072][768]
#define W2_OFF (4*768*768 + 768*3072)      // [768][3072]
#define WTOT   (4*768*768 + 2*768*3072)

// ---------------- scratch (device globals; no allocation allowed) ----------------
__device__ float g_R1 [MTOK * DMODEL];
__device__ float g_H  [MTOK * DMODEL];
__device__ float g_R2 [MTOK * DMODEL];
__device__ __half g_qh [MTOK * DMODEL];          // Q single
__device__ __half g_kh [MTOK * DMODEL];          // K hi
__device__ __half g_kl [MTOK * DMODEL];          // K lo
__device__ __half g_vh [MTOK * DMODEL];          // V hi
__device__ __half g_vl [MTOK * DMODEL];          // V lo
__device__ __half g_act[MTOK * DMODEL];          // x / attn-out / H single
__device__ __half g_ff [MTOK * DFF];             // FF single
__device__ __half g_bhi[WTOT];
__device__ __half g_blo[WTOT];

// ---------------- helpers ----------------
__device__ __forceinline__ uint32_t smem_u32(const void* p) {
    uint32_t a;
    asm("{ .reg .u64 t; cvta.to.shared.u64 t, %1; cvt.u32.u64 %0, t; }" : "=r"(a) : "l"(p));
    return a;
}
__device__ __forceinline__ void cp16(uint32_t d, const void* s) {
    asm volatile("cp.async.cg.shared.global [%0], [%1], 16;" :: "r"(d), "l"(s));
}
#define CP_COMMIT() asm volatile("cp.async.commit_group;" ::: "memory")
#define CP_WAIT0()  asm volatile("cp.async.wait_group 0;"  ::: "memory")
#define CP_WAIT1()  asm volatile("cp.async.wait_group 1;"  ::: "memory")

#define LDSM4(r0, r1, r2, r3, addr) \
    asm volatile("ldmatrix.sync.aligned.m8n8.x4.shared.b16 {%0,%1,%2,%3}, [%4];" \
        : "=r"(r0), "=r"(r1), "=r"(r2), "=r"(r3) : "r"(addr))
#define LDSM4T(r0, r1, r2, r3, addr) \
    asm volatile("ldmatrix.sync.aligned.m8n8.x4.trans.shared.b16 {%0,%1,%2,%3}, [%4];" \
        : "=r"(r0), "=r"(r1), "=r"(r2), "=r"(r3) : "r"(addr))

#define MMA16816(c, a, b) \
    asm volatile("mma.sync.aligned.m16n8k16.row.col.f32.f16.f16.f32 " \
        "{%0,%1,%2,%3},{%4,%5,%6,%7},{%8,%9},{%0,%1,%2,%3};" \
        : "+f"((c)[0]), "+f"((c)[1]), "+f"((c)[2]), "+f"((c)[3]) \
        : "r"((a)[0]), "r"((a)[1]), "r"((a)[2]), "r"((a)[3]), \
          "r"((b)[0]), "r"((b)[1]))

__device__ __forceinline__ void split_store(float v, __half* hi, __half* lo) {
    __half h = __float2half_rn(v);
    *hi = h;
    *lo = __float2half_rn(v - __half2float(h));
}
__device__ __forceinline__ uint32_t pack2h(float a, float b) {
    __half2 h = __floats2half2_rn(a, b);
    return *(uint32_t*)&h;
}

// =================================================================
// mma.sync GEMM (fp16, 2-term): C[M,N] = A[M,K] @ Bt[N,K]^T (+bias)(+res)(+relu)
// A single fp16; B split hi/lo fp16. D = A*Bh + A*Bl, fp32 accum.
// Block 128x128, BK=32, 256 threads (8 warps, 64x32 each). 2-stage cp.async.
// =================================================================
#define BKG   32
#define ROWB  80
#define TILEB 10240
#define STAGEB (3 * TILEB)            // A, Bh, Bl
#define GEMM_SMEM (2 * STAGEB)        // 61440 B

__device__ __forceinline__ void load_stage(
    uint32_t st, const __half* A, const __half* Bh, const __half* Bl,
    int bm, int bn, int k0, int K, int tid)
{
#pragma unroll
    for (int i = 0; i < 6; i++) {
        int idx = tid + i * 256;          // 0..1535
        int t   = idx >> 9;               // 0=A 1=Bh 2=Bl
        int rem = idx & 511;
        int r   = rem >> 2;               // row 0..127
        int kc  = (rem & 3) * 8;
        uint32_t so = (uint32_t)(r * ROWB + kc * 2);
        const __half* src = (t == 0) ? A : (t == 1) ? Bh : Bl;
        int base = (t == 0) ? bm : bn;
        cp16(st + t * TILEB + so, src + (size_t)(base + r) * K + k0 + kc);
    }
}

__global__ __launch_bounds__(256, 1)
void gemm_mma(const __half* __restrict__ A,
              const __half* __restrict__ Bh, const __half* __restrict__ Bl,
              const float* __restrict__ bias, const float* __restrict__ res,
              float* __restrict__ C, __half* __restrict__ Chi,
              __half* __restrict__ Clo, int N, int K, int relu)
{
    extern __shared__ char smem[];
    const uint32_t sb = smem_u32(smem);
    const int tid = threadIdx.x;
    const int wid = tid >> 5, lane = tid & 31;
    const int wm = wid & 1;
    const int wn = wid >> 1;
    const int bm = blockIdx.y * 128, bn = blockIdx.x * 128;

    float acc[4][4][4];
#pragma unroll
    for (int mt = 0; mt < 4; mt++)
#pragma unroll
        for (int nt = 0; nt < 4; nt++)
#pragma unroll
            for (int i = 0; i < 4; i++) acc[mt][nt][i] = 0.f;

    const int nk = K / BKG;
    load_stage(sb, A, Bh, Bl, bm, bn, 0, K, tid);
    CP_COMMIT();

    for (int ks = 0; ks < nk; ks++) {
        if (ks + 1 < nk) {
            load_stage(sb + ((ks + 1) & 1) * STAGEB, A, Bh, Bl,
                       bm, bn, (ks + 1) * BKG, K, tid);
            CP_COMMIT();
            CP_WAIT1();
        } else {
            CP_WAIT0();
        }
        __syncthreads();

        const uint32_t st = sb + (ks & 1) * STAGEB;
#pragma unroll
        for (int kk = 0; kk < 2; kk++) {
            uint32_t af[4][4];
            uint32_t aoff = st + (uint32_t)((wm * 64 + (lane & 15)) * ROWB)
                          + kk * 32 + ((lane >> 4) & 1) * 16;
#pragma unroll
            for (int mt = 0; mt < 4; mt++)
                LDSM4(af[mt][0], af[mt][1], af[mt][2], af[mt][3], aoff + mt * 16 * ROWB);

            uint32_t bh[4][2], bl[4][2];
            uint32_t boff = st + TILEB
                          + (uint32_t)((wn * 32 + (lane & 7) + ((lane >> 4) & 1) * 8) * ROWB)
                          + kk * 32 + ((lane >> 3) & 1) * 16;
#pragma unroll
            for (int np = 0; np < 2; np++) {
                uint32_t r0, r1, r2, r3;
                LDSM4(r0, r1, r2, r3, boff + np * 16 * ROWB);
                bh[2*np][0] = r0; bh[2*np][1] = r1; bh[2*np+1][0] = r2; bh[2*np+1][1] = r3;
                LDSM4(r0, r1, r2, r3, boff + TILEB + np * 16 * ROWB);
                bl[2*np][0] = r0; bl[2*np][1] = r1; bl[2*np+1][0] = r2; bl[2*np+1][1] = r3;
            }
#pragma unroll
            for (int mt = 0; mt < 4; mt++)
#pragma unroll
                for (int nt = 0; nt < 4; nt++) {
                    MMA16816(acc[mt][nt], af[mt], bh[nt]);
                    MMA16816(acc[mt][nt], af[mt], bl[nt]);
                }
        }
        __syncthreads();
    }

#pragma unroll
    for (int mt = 0; mt < 4; mt++)
#pragma unroll
        for (int nt = 0; nt < 4; nt++) {
            int row = bm + wm * 64 + mt * 16 + (lane >> 2);
            int col = bn + wn * 32 + nt * 8 + (lane & 3) * 2;
            float b0 = bias[col], b1 = bias[col + 1];
#pragma unroll
            for (int half = 0; half < 2; half++) {
                int r = row + half * 8;
                size_t idx = (size_t)r * N + col;
                float v0 = acc[mt][nt][half * 2 + 0] + b0;
                float v1 = acc[mt][nt][half * 2 + 1] + b1;
                if (res) {
                    float2 rv = *(const float2*)&res[idx];
                    v0 += rv.x; v1 += rv.y;
                }
                if (relu) { v0 = fmaxf(v0, 0.f); v1 = fmaxf(v1, 0.f); }
                if (C) { float2 o = make_float2(v0, v1); *(float2*)&C[idx] = o; }
                if (Chi) {
                    __half2 hp = __floats2half2_rn(v0, v1);
                    *(__half2*)&Chi[idx] = hp;
                    if (Clo) {
                        __half2 lp;
                        lp.x = __float2half_rn(v0 - __half2float(hp.x));
                        lp.y = __float2half_rn(v1 - __half2float(hp.y));
                        *(__half2*)&Clo[idx] = lp;
                    }
                }
            }
        }
}

// =================================================================
// Weight transpose + split: W[K,N] fp32 -> Th/Tl[N,K] fp16
// =================================================================
__global__ void wsplit_kernel(const float* __restrict__ W, __half* __restrict__ Th,
                              __half* __restrict__ Tl, int Kd, int Nd)
{
    __shared__ float t[32][33];
    int k0 = blockIdx.x * 32, n0 = blockIdx.y * 32;
    int tx = threadIdx.x, ty = threadIdx.y;
    for (int i = ty; i < 32; i += 8)
        t[i][tx] = W[(size_t)(k0 + i) * Nd + n0 + tx];
    __syncthreads();
    for (int i = ty; i < 32; i += 8) {
        float v = t[tx][i];
        size_t o = (size_t)(n0 + i) * Kd + k0 + tx;
        split_store(v, &Th[o], &Tl[o]);
    }
}

// activation fp32 -> single fp16
__global__ void asplit_kernel(const float* __restrict__ A, __half* __restrict__ Ah)
{
    int i = (blockIdx.x * blockDim.x + threadIdx.x) * 4;
    float4 v = *(const float4*)&A[i];
    __half2 a = __floats2half2_rn(v.x, v.y);
    __half2 b = __floats2half2_rn(v.z, v.w);
    *(__half2*)&Ah[i]     = a;
    *(__half2*)&Ah[i + 2] = b;
}

// =================================================================
// Flash attention (causal) on mma.sync, fp16 2-term.
// Q single fp16; K,V split hi/lo; P single fp16.
// Block: 128 queries x (head,batch); 8 warps, 16 rows each; 64-key chunks.
// =================================================================
#define APITCH   144
#define AST_OFF  18432               // Q single: 128*144
#define AKH 0
#define AKL 9216
#define AVH 18432
#define AVL 27648
#define AST_SZ   36864
#define ATT_SMEM (AST_OFF + 2 * AST_SZ)   // 92160 B

__device__ __forceinline__ void att_load_kv(
    uint32_t stbase, const __half* Kh, const __half* Kl,
    const __half* Vh, const __half* Vl,
    int b, int h, int j0, int tid)
{
#pragma unroll
    for (int i = 0; i < 8; i++) {
        int idx = tid + i * 256;          // 0..2047
        int t   = idx >> 9;               // 0=Kh 1=Kl 2=Vh 3=Vl
        int rem = idx & 511;
        int r   = rem >> 3;               // row 0..63
        int c   = (rem & 7) * 8;
        size_t go = (size_t)(b * TSEQ + j0 + r) * DMODEL + h * DHEAD + c;
        const __half* src = (t == 0) ? Kh : (t == 1) ? Kl : (t == 2) ? Vh : Vl;
        cp16(stbase + t * 9216 + r * APITCH + c * 2, src + go);
    }
}

__global__ __launch_bounds__(256, 1)
void attn_mma(const __half* __restrict__ Qh,
              const __half* __restrict__ Kh, const __half* __restrict__ Kl,
              const __half* __restrict__ Vh, const __half* __restrict__ Vl,
              __half* __restrict__ Oh)
{
    extern __shared__ char smem[];
    const uint32_t sb = smem_u32(smem);
    const int tid = threadIdx.x;
    const int wid = tid >> 5, lane = tid & 31;
    const int q0 = (gridDim.x - 1 - blockIdx.x) * 128;   // long blocks first
    const int h  = blockIdx.y;
    const int b  = blockIdx.z;

    // ---- load Q tile (single): 1024 cp16, 4 per thread ----
#pragma unroll
    for (int i = 0; i < 4; i++) {
        int idx = tid + i * 256;          // 0..1023
        int r   = idx >> 3;               // 0..127
        int c   = (idx & 7) * 8;
        size_t go = (size_t)(b * TSEQ + q0 + r) * DMODEL + h * DHEAD + c;
        cp16(sb + r * APITCH + c * 2, Qh + go);
    }
    CP_COMMIT();

    const int nch = q0 / 64 + 2;
    att_load_kv(sb + AST_OFF, Kh, Kl, Vh, Vl, b, h, 0, tid);
    CP_COMMIT();

    float m2[2] = {-1e30f, -1e30f};
    float l2[2] = {0.f, 0.f};
    float o[8][4];
#pragma unroll
    for (int nt = 0; nt < 8; nt++)
#pragma unroll
        for (int i = 0; i < 4; i++) o[nt][i] = 0.f;

    const int r0g = q0 + wid * 16 + (lane >> 2);

    for (int ci = 0; ci < nch; ci++) {
        __syncthreads();
        if (ci + 1 < nch) {
            att_load_kv(sb + AST_OFF + ((ci + 1) & 1) * AST_SZ,
                        Kh, Kl, Vh, Vl, b, h, (ci + 1) * 64, tid);
            CP_COMMIT();
            CP_WAIT1();
        } else {
            CP_WAIT0();
        }
        __syncthreads();

        const uint32_t st = sb + AST_OFF + (ci & 1) * AST_SZ;
        const int j0 = ci * 64;

        // ---- S = Q K^T (2-term) ----
        float s[8][4];
#pragma unroll
        for (int nt = 0; nt < 8; nt++)
#pragma unroll
            for (int i = 0; i < 4; i++) s[nt][i] = 0.f;

#pragma unroll
        for (int kk = 0; kk < 4; kk++) {
            uint32_t qa[4];
            uint32_t aoff = sb + (uint32_t)((wid * 16 + (lane & 15)) * APITCH)
                          + kk * 32 + ((lane >> 4) & 1) * 16;
            LDSM4(qa[0], qa[1], qa[2], qa[3], aoff);
#pragma unroll
            for (int np = 0; np < 4; np++) {
                uint32_t boff = st + AKH
                              + (uint32_t)((np * 16 + (lane & 7) + ((lane >> 4) & 1) * 8) * APITCH)
                              + kk * 32 + ((lane >> 3) & 1) * 16;
                uint32_t k0r, k1r, k2r, k3r;
                LDSM4(k0r, k1r, k2r, k3r, boff);
                uint32_t l0r, l1r, l2r, l3r;
                LDSM4(l0r, l1r, l2r, l3r, boff + (AKL - AKH));
                uint32_t bh0[2] = {k0r, k1r}, bh1[2] = {k2r, k3r};
                uint32_t bl0[2] = {l0r, l1r}, bl1[2] = {l2r, l3r};
                MMA16816(s[2*np],   qa, bh0);
                MMA16816(s[2*np],   qa, bl0);
                MMA16816(s[2*np+1], qa, bh1);
                MMA16816(s[2*np+1], qa, bl1);
            }
        }

        // ---- scale + causal mask ----
#pragma unroll
        for (int nt = 0; nt < 8; nt++)
#pragma unroll
            for (int i = 0; i < 4; i++) s[nt][i] *= 0.125f;

        if (j0 >= q0) {
#pragma unroll
            for (int nt = 0; nt < 8; nt++) {
                int col = j0 + nt * 8 + (lane & 3) * 2;
                if (col     > r0g)     s[nt][0] = -1e30f;
                if (col + 1 > r0g)     s[nt][1] = -1e30f;
                if (col     > r0g + 8) s[nt][2] = -1e30f;
                if (col + 1 > r0g + 8) s[nt][3] = -1e30f;
            }
        }

        // ---- streaming softmax ----
#pragma unroll
        for (int rh = 0; rh < 2; rh++) {
            float cm = -1e30f;
#pragma unroll
            for (int nt = 0; nt < 8; nt++)
                cm = fmaxf(cm, fmaxf(s[nt][rh*2], s[nt][rh*2+1]));
            cm = fmaxf(cm, __shfl_xor_sync(0xffffffffu, cm, 1));
            cm = fmaxf(cm, __shfl_xor_sync(0xffffffffu, cm, 2));
            float mn = fmaxf(m2[rh], cm);
            float corr = __expf(m2[rh] - mn);
            m2[rh] = mn;
            float rs = 0.f;
#pragma unroll
            for (int nt = 0; nt < 8; nt++) {
                float p0 = __expf(s[nt][rh*2]   - mn);
                float p1 = __expf(s[nt][rh*2+1] - mn);
                s[nt][rh*2] = p0; s[nt][rh*2+1] = p1;
                rs += p0 + p1;
            }
            rs += __shfl_xor_sync(0xffffffffu, rs, 1);
            rs += __shfl_xor_sync(0xffffffffu, rs, 2);
            l2[rh] = l2[rh] * corr + rs;
#pragma unroll
            for (int nt = 0; nt < 8; nt++) {
                o[nt][rh*2]   *= corr;
                o[nt][rh*2+1] *= corr;
            }
        }

        // ---- O += P V (2-term); P single fp16 from registers ----
#pragma unroll
        for (int kc = 0; kc < 4; kc++) {
            uint32_t ph[4];
            ph[0] = pack2h(s[2*kc][0],   s[2*kc][1]);
            ph[1] = pack2h(s[2*kc][2],   s[2*kc][3]);
            ph[2] = pack2h(s[2*kc+1][0], s[2*kc+1][1]);
            ph[3] = pack2h(s[2*kc+1][2], s[2*kc+1][3]);
#pragma unroll
            for (int np = 0; np < 4; np++) {
                uint32_t voff = st + AVH
                              + (uint32_t)((kc * 16 + (lane & 15)) * APITCH)
                              + (np * 16 + ((lane >> 4) & 1) * 8) * 2;
                uint32_t v0r, v1r, v2r, v3r;
                LDSM4T(v0r, v1r, v2r, v3r, voff);
                uint32_t w0r, w1r, w2r, w3r;
                LDSM4T(w0r, w1r, w2r, w3r, voff + (AVL - AVH));
                uint32_t vh0[2] = {v0r, v1r}, vh1[2] = {v2r, v3r};
                uint32_t vl0[2] = {w0r, w1r}, vl1[2] = {w2r, w3r};
                MMA16816(o[2*np],   ph, vh0);
                MMA16816(o[2*np],   ph, vl0);
                MMA16816(o[2*np+1], ph, vh1);
                MMA16816(o[2*np+1], ph, vl1);
            }
        }
    }

    // ---- normalize + write single fp16 ----
    float inv0 = 1.f / l2[0], inv1 = 1.f / l2[1];
#pragma unroll
    for (int nt = 0; nt < 8; nt++) {
        int col = h * DHEAD + nt * 8 + (lane & 3) * 2;
        size_t i0 = (size_t)(b * TSEQ + r0g) * DMODEL + col;
        size_t i1 = (size_t)(b * TSEQ + r0g + 8) * DMODEL + col;
        *(__half2*)&Oh[i0] = __floats2half2_rn(o[nt][0] * inv0, o[nt][1] * inv0);
        *(__half2*)&Oh[i1] = __floats2half2_rn(o[nt][2] * inv1, o[nt][3] * inv1);
    }
}

// =================================================================
// LayerNorm; optionally also emits single fp16 of the output.
// =================================================================
__global__ __launch_bounds__(256)
void ln_kernel(const float* __restrict__ in, const float* __restrict__ g,
               const float* __restrict__ be, float* __restrict__ out,
               __half* __restrict__ Oh)
{
    const int row = blockIdx.x;
    const int tid = threadIdx.x;
    const float* xr = in + (size_t)row * DMODEL;

    float v0 = xr[tid], v1 = xr[tid + 256], v2 = xr[tid + 512];
    float s = v0 + v1 + v2;
    float s2 = v0 * v0 + v1 * v1 + v2 * v2;

    __shared__ float rs[8], rs2[8], stats[2];
#pragma unroll
    for (int off = 16; off; off >>= 1) {
        s  += __shfl_xor_sync(0xffffffffu, s,  off);
        s2 += __shfl_xor_sync(0xffffffffu, s2, off);
    }
    int w = tid >> 5, lane = tid & 31;
    if (lane == 0) { rs[w] = s; rs2[w] = s2; }
    __syncthreads();
    if (tid == 0) {
        float S = 0.f, S2 = 0.f;
#pragma unroll
        for (int i = 0; i < 8; i++) { S += rs[i]; S2 += rs2[i]; }
        float mean = S * (1.f / DMODEL);
        float var  = S2 * (1.f / DMODEL) - mean * mean;
        stats[0] = mean;
        stats[1] = rsqrtf(var + 1e-5f);
    }
    __syncthreads();
    float mean = stats[0], r = stats[1];
    size_t rb = (size_t)row * DMODEL;
    float vv[3] = {v0, v1, v2};
#pragma unroll
    for (int p = 0; p < 3; p++) {
        int c = tid + p * 256;
        float y = (vv[p] - mean) * r * g[c] + be[c];
        out[rb + c] = y;
        if (Oh) Oh[rb + c] = __float2half_rn(y);
    }
}

// =================================================================
// Host launch
// =================================================================
extern "C" void kernel_launch(void* const* d_in, const int* in_sizes, int n_in,
                              void* d_out, int out_size)
{
    const float* x  = (const float*)d_in[0];
    const float* wq = (const float*)d_in[1];
    const float* bq = (const float*)d_in[2];
    const float* wk = (const float*)d_in[3];
    const float* bk = (const float*)d_in[4];
    const float* wv = (const float*)d_in[5];
    const float* bv = (const float*)d_in[6];
    const float* wo = (const float*)d_in[7];
    const float* bo = (const float*)d_in[8];
    const float* w1 = (const float*)d_in[9];
    const float* b1 = (const float*)d_in[10];
    const float* w2 = (const float*)d_in[11];
    const float* b2 = (const float*)d_in[12];
    const float* g1 = (const float*)d_in[13];
    const float* be1= (const float*)d_in[14];
    const float* g2 = (const float*)d_in[15];
    const float* be2= (const float*)d_in[16];
    float* out = (float*)d_out;

    float *R1, *H, *R2;
    __half *Qh, *Kh, *Kl, *Vh, *Vl, *Act, *FF, *Bh, *Bl;
    cudaGetSymbolAddress((void**)&R1,  g_R1);
    cudaGetSymbolAddress((void**)&H,   g_H);
    cudaGetSymbolAddress((void**)&R2,  g_R2);
    cudaGetSymbolAddress((void**)&Qh,  g_qh);
    cudaGetSymbolAddress((void**)&Kh,  g_kh);
    cudaGetSymbolAddress((void**)&Kl,  g_kl);
    cudaGetSymbolAddress((void**)&Vh,  g_vh);
    cudaGetSymbolAddress((void**)&Vl,  g_vl);
    cudaGetSymbolAddress((void**)&Act, g_act);
    cudaGetSymbolAddress((void**)&FF,  g_ff);
    cudaGetSymbolAddress((void**)&Bh,  g_bhi);
    cudaGetSymbolAddress((void**)&Bl,  g_blo);

    cudaFuncSetAttribute(attn_mma, cudaFuncAttributeMaxDynamicSharedMemorySize, ATT_SMEM);
    cudaFuncSetAttribute(gemm_mma, cudaFuncAttributeMaxDynamicSharedMemorySize, GEMM_SMEM);

    // weight transpose + hi/lo split (fp16)
    dim3 tb(32, 8);
    const float*  wsrc[6] = {wq, wk, wv, wo, w1, w2};
    const size_t  offs[6] = {WQ_OFF, WK_OFF, WV_OFF, WO_OFF, W1_OFF, W2_OFF};
    const int     wkd[6]  = {768, 768, 768, 768, 768, 3072};
    const int     wnd[6]  = {768, 768, 768, 768, 3072, 768};
    for (int i = 0; i < 6; i++)
        wsplit_kernel<<<dim3(wkd[i] / 32, wnd[i] / 32), tb>>>(
            wsrc[i], Bh + offs[i], Bl + offs[i], wkd[i], wnd[i]);

    // x -> single fp16
    asplit_kernel<<<MTOK * DMODEL / 1024, 256>>>(x, Act);

    dim3 gD(DMODEL / 128, MTOK / 128);  // (6, 64)
    dim3 gF(DFF / 128,    MTOK / 128);  // (24, 64)

    // QKV projections: Q single; K,V hi/lo
    gemm_mma<<<gD, 256, GEMM_SMEM>>>(Act, Bh + WQ_OFF, Bl + WQ_OFF, bq, nullptr, nullptr, Qh, nullptr, DMODEL, DMODEL, 0);
    gemm_mma<<<gD, 256, GEMM_SMEM>>>(Act, Bh + WK_OFF, Bl + WK_OFF, bk, nullptr, nullptr, Kh, Kl, DMODEL, DMODEL, 0);
    gemm_mma<<<gD, 256, GEMM_SMEM>>>(Act, Bh + WV_OFF, Bl + WV_OFF, bv, nullptr, nullptr, Vh, Vl, DMODEL, DMODEL, 0);

    // causal flash attention -> attn out single fp16 into Act
    attn_mma<<<dim3(TSEQ / 128, NHEADS, BBATCH), 256, ATT_SMEM>>>(Qh, Kh, Kl, Vh, Vl, Act);

    // output projection + residual(x), LN1 (emits H single into Act)
    gemm_mma<<<gD, 256, GEMM_SMEM>>>(Act, Bh + WO_OFF, Bl + WO_OFF, bo, x, R1, nullptr, nullptr, DMODEL, DMODEL, 0);
    ln_kernel<<<MTOK, 256>>>(R1, g1, be1, H, Act);

    // FFN: W1 (+relu) -> FF single; W2 + residual(H)
    gemm_mma<<<gF, 256, GEMM_SMEM>>>(Act, Bh + W1_OFF, Bl + W1_OFF, b1, nullptr, nullptr, FF, nullptr, DFF, DMODEL, 1);
    gemm_mma<<<gD, 256, GEMM_SMEM>>>(FF,  Bh + W2_OFF, Bl + W2_OFF, b2, H, R2, nullptr, nullptr, DMODEL, DFF, 0);

    // LN2 -> output
    ln_kernel<<<MTOK, 256>>>(R2, g2, be2, out, nullptr);
}

// round 14
// speedup vs baseline: 5.5348x; 1.5140x over previous
#include <cuda_runtime.h>
#include <cuda_fp16.h>
#include <stdint.h>
#include <math.h>

// ---------------- problem constants ----------------
#define DMODEL 768
#define NHEADS 12
#define DHEAD  64
#define DFF    3072
#define BBATCH 2
#define TSEQ   4096
#define MTOK   (BBATCH * TSEQ)   // 8192 tokens

// weight (transposed [N,K], fp16) offsets inside g_w
#define WQ_OFF 0
#define WK_OFF (768*768)
#define WV_OFF (2*768*768)
#define WO_OFF (3*768*768)
#define W1_OFF (4*768*768)                 // [3072][768]
#define W2_OFF (4*768*768 + 768*3072)      // [768][3072]
#define WTOT   (4*768*768 + 2*768*3072)

// ---------------- scratch (device globals; no allocation allowed) ----------------
__device__ float g_R1 [MTOK * DMODEL];
__device__ float g_H  [MTOK * DMODEL];
__device__ float g_R2 [MTOK * DMODEL];
__device__ __half g_qh [MTOK * DMODEL];
__device__ __half g_kh [MTOK * DMODEL];
__device__ __half g_vh [MTOK * DMODEL];
__device__ __half g_act[MTOK * DMODEL];
__device__ __half g_ff [MTOK * DFF];
__device__ __half g_w  [WTOT];

// ---------------- helpers ----------------
__device__ __forceinline__ uint32_t smem_u32(const void* p) {
    uint32_t a;
    asm("{ .reg .u64 t; cvta.to.shared.u64 t, %1; cvt.u32.u64 %0, t; }" : "=r"(a) : "l"(p));
    return a;
}
__device__ __forceinline__ void cp16(uint32_t d, const void* s) {
    asm volatile("cp.async.cg.shared.global [%0], [%1], 16;" :: "r"(d), "l"(s));
}
#define CP_COMMIT() asm volatile("cp.async.commit_group;" ::: "memory")
#define CP_WAIT0()  asm volatile("cp.async.wait_group 0;"  ::: "memory")
#define CP_WAIT1()  asm volatile("cp.async.wait_group 1;"  ::: "memory")

#define LDSM4(r0, r1, r2, r3, addr) \
    asm volatile("ldmatrix.sync.aligned.m8n8.x4.shared.b16 {%0,%1,%2,%3}, [%4];" \
        : "=r"(r0), "=r"(r1), "=r"(r2), "=r"(r3) : "r"(addr))
#define LDSM4T(r0, r1, r2, r3, addr) \
    asm volatile("ldmatrix.sync.aligned.m8n8.x4.trans.shared.b16 {%0,%1,%2,%3}, [%4];" \
        : "=r"(r0), "=r"(r1), "=r"(r2), "=r"(r3) : "r"(addr))

#define MMA16816(c, a, b) \
    asm volatile("mma.sync.aligned.m16n8k16.row.col.f32.f16.f16.f32 " \
        "{%0,%1,%2,%3},{%4,%5,%6,%7},{%8,%9},{%0,%1,%2,%3};" \
        : "+f"((c)[0]), "+f"((c)[1]), "+f"((c)[2]), "+f"((c)[3]) \
        : "r"((a)[0]), "r"((a)[1]), "r"((a)[2]), "r"((a)[3]), \
          "r"((b)[0]), "r"((b)[1]))

__device__ __forceinline__ uint32_t pack2h(float a, float b) {
    __half2 h = __floats2half2_rn(a, b);
    return *(uint32_t*)&h;
}

// =================================================================
// mma.sync GEMM (pure fp16): C[M,N] = A[M,K] @ Bt[N,K]^T (+bias)(+res)(+relu)
// fp32 accumulation. Block 128x128, BK=32, 256 threads (8 warps, 64x32 each).
// 2-stage cp.async pipeline. Rows padded to 40 fp16 (80B).
// =================================================================
#define BKG   32
#define ROWB  80
#define TILEB 10240
#define STAGEB (2 * TILEB)            // A, B
#define GEMM_SMEM (2 * STAGEB)        // 40960 B

__device__ __forceinline__ void load_stage(
    uint32_t st, const __half* A, const __half* B,
    int bm, int bn, int k0, int K, int tid)
{
#pragma unroll
    for (int i = 0; i < 4; i++) {
        int idx = tid + i * 256;          // 0..1023
        int t   = idx >> 9;               // 0=A 1=B
        int rem = idx & 511;
        int r   = rem >> 2;               // row 0..127
        int kc  = (rem & 3) * 8;
        uint32_t so = (uint32_t)(r * ROWB + kc * 2);
        const __half* src = t ? B : A;
        int base = t ? bn : bm;
        cp16(st + t * TILEB + so, src + (size_t)(base + r) * K + k0 + kc);
    }
}

__global__ __launch_bounds__(256, 1)
void gemm_mma(const __half* __restrict__ A, const __half* __restrict__ B,
              const float* __restrict__ bias, const float* __restrict__ res,
              float* __restrict__ C, __half* __restrict__ Chf,
              int N, int K, int relu)
{
    extern __shared__ char smem[];
    const uint32_t sb = smem_u32(smem);
    const int tid = threadIdx.x;
    const int wid = tid >> 5, lane = tid & 31;
    const int wm = wid & 1;
    const int wn = wid >> 1;
    const int bm = blockIdx.y * 128, bn = blockIdx.x * 128;

    float acc[4][4][4];
#pragma unroll
    for (int mt = 0; mt < 4; mt++)
#pragma unroll
        for (int nt = 0; nt < 4; nt++)
#pragma unroll
            for (int i = 0; i < 4; i++) acc[mt][nt][i] = 0.f;

    const int nk = K / BKG;
    load_stage(sb, A, B, bm, bn, 0, K, tid);
    CP_COMMIT();

    for (int ks = 0; ks < nk; ks++) {
        if (ks + 1 < nk) {
            load_stage(sb + ((ks + 1) & 1) * STAGEB, A, B,
                       bm, bn, (ks + 1) * BKG, K, tid);
            CP_COMMIT();
            CP_WAIT1();
        } else {
            CP_WAIT0();
        }
        __syncthreads();

        const uint32_t st = sb + (ks & 1) * STAGEB;
#pragma unroll
        for (int kk = 0; kk < 2; kk++) {
            uint32_t af[4][4];
            uint32_t aoff = st + (uint32_t)((wm * 64 + (lane & 15)) * ROWB)
                          + kk * 32 + ((lane >> 4) & 1) * 16;
#pragma unroll
            for (int mt = 0; mt < 4; mt++)
                LDSM4(af[mt][0], af[mt][1], af[mt][2], af[mt][3], aoff + mt * 16 * ROWB);

            uint32_t bf[4][2];
            uint32_t boff = st + TILEB
                          + (uint32_t)((wn * 32 + (lane & 7) + ((lane >> 4) & 1) * 8) * ROWB)
                          + kk * 32 + ((lane >> 3) & 1) * 16;
#pragma unroll
            for (int np = 0; np < 2; np++) {
                uint32_t r0, r1, r2, r3;
                LDSM4(r0, r1, r2, r3, boff + np * 16 * ROWB);
                bf[2*np][0] = r0; bf[2*np][1] = r1; bf[2*np+1][0] = r2; bf[2*np+1][1] = r3;
            }
#pragma unroll
            for (int mt = 0; mt < 4; mt++)
#pragma unroll
                for (int nt = 0; nt < 4; nt++)
                    MMA16816(acc[mt][nt], af[mt], bf[nt]);
        }
        __syncthreads();
    }

#pragma unroll
    for (int mt = 0; mt < 4; mt++)
#pragma unroll
        for (int nt = 0; nt < 4; nt++) {
            int row = bm + wm * 64 + mt * 16 + (lane >> 2);
            int col = bn + wn * 32 + nt * 8 + (lane & 3) * 2;
            float b0 = bias[col], b1 = bias[col + 1];
#pragma unroll
            for (int half = 0; half < 2; half++) {
                int r = row + half * 8;
                size_t idx = (size_t)r * N + col;
                float v0 = acc[mt][nt][half * 2 + 0] + b0;
                float v1 = acc[mt][nt][half * 2 + 1] + b1;
                if (res) {
                    float2 rv = *(const float2*)&res[idx];
                    v0 += rv.x; v1 += rv.y;
                }
                if (relu) { v0 = fmaxf(v0, 0.f); v1 = fmaxf(v1, 0.f); }
                if (C) { float2 o = make_float2(v0, v1); *(float2*)&C[idx] = o; }
                if (Chf) *(__half2*)&Chf[idx] = __floats2half2_rn(v0, v1);
            }
        }
}

// =================================================================
// Weight transpose: W[K,N] fp32 -> T[N,K] fp16
// =================================================================
__global__ void wsplit_kernel(const float* __restrict__ W, __half* __restrict__ T,
                              int Kd, int Nd)
{
    __shared__ float t[32][33];
    int k0 = blockIdx.x * 32, n0 = blockIdx.y * 32;
    int tx = threadIdx.x, ty = threadIdx.y;
    for (int i = ty; i < 32; i += 8)
        t[i][tx] = W[(size_t)(k0 + i) * Nd + n0 + tx];
    __syncthreads();
    for (int i = ty; i < 32; i += 8)
        T[(size_t)(n0 + i) * Kd + k0 + tx] = __float2half_rn(t[tx][i]);
}

// activation fp32 -> fp16
__global__ void asplit_kernel(const float* __restrict__ A, __half* __restrict__ Ah)
{
    int i = (blockIdx.x * blockDim.x + threadIdx.x) * 4;
    float4 v = *(const float4*)&A[i];
    *(__half2*)&Ah[i]     = __floats2half2_rn(v.x, v.y);
    *(__half2*)&Ah[i + 2] = __floats2half2_rn(v.z, v.w);
}

// =================================================================
// Flash attention (causal) on mma.sync, pure fp16 operands, fp32 softmax.
// Block: 128 queries x (head,batch); 8 warps, 16 rows each; 64-key chunks.
// =================================================================
#define APITCH   144
#define AST_OFF  18432               // Q: 128*144
#define AVH 9216
#define AST_SZ   18432               // K + V tiles
#define ATT_SMEM (AST_OFF + 2 * AST_SZ)   // 55296 B

__device__ __forceinline__ void att_load_kv(
    uint32_t stbase, const __half* Kh, const __half* Vh,
    int b, int h, int j0, int tid)
{
#pragma unroll
    for (int i = 0; i < 4; i++) {
        int idx = tid + i * 256;          // 0..1023
        int t   = idx >> 9;               // 0=K 1=V
        int rem = idx & 511;
        int r   = rem >> 3;               // row 0..63
        int c   = (rem & 7) * 8;
        size_t go = (size_t)(b * TSEQ + j0 + r) * DMODEL + h * DHEAD + c;
        cp16(stbase + t * AVH + r * APITCH + c * 2, (t ? Vh : Kh) + go);
    }
}

__global__ __launch_bounds__(256, 1)
void attn_mma(const __half* __restrict__ Qh,
              const __half* __restrict__ Kh, const __half* __restrict__ Vh,
              __half* __restrict__ Oh)
{
    extern __shared__ char smem[];
    const uint32_t sb = smem_u32(smem);
    const int tid = threadIdx.x;
    const int wid = tid >> 5, lane = tid & 31;
    const int q0 = (gridDim.x - 1 - blockIdx.x) * 128;   // long blocks first
    const int h  = blockIdx.y;
    const int b  = blockIdx.z;

    // ---- load Q tile ----
#pragma unroll
    for (int i = 0; i < 4; i++) {
        int idx = tid + i * 256;
        int r   = idx >> 3;
        int c   = (idx & 7) * 8;
        size_t go = (size_t)(b * TSEQ + q0 + r) * DMODEL + h * DHEAD + c;
        cp16(sb + r * APITCH + c * 2, Qh + go);
    }
    CP_COMMIT();

    const int nch = q0 / 64 + 2;
    att_load_kv(sb + AST_OFF, Kh, Vh, b, h, 0, tid);
    CP_COMMIT();

    float m2[2] = {-1e30f, -1e30f};
    float l2[2] = {0.f, 0.f};
    float o[8][4];
#pragma unroll
    for (int nt = 0; nt < 8; nt++)
#pragma unroll
        for (int i = 0; i < 4; i++) o[nt][i] = 0.f;

    const int r0g = q0 + wid * 16 + (lane >> 2);

    for (int ci = 0; ci < nch; ci++) {
        __syncthreads();
        if (ci + 1 < nch) {
            att_load_kv(sb + AST_OFF + ((ci + 1) & 1) * AST_SZ,
                        Kh, Vh, b, h, (ci + 1) * 64, tid);
            CP_COMMIT();
            CP_WAIT1();
        } else {
            CP_WAIT0();
        }
        __syncthreads();

        const uint32_t st = sb + AST_OFF + (ci & 1) * AST_SZ;
        const int j0 = ci * 64;

        // ---- S = Q K^T ----
        float s[8][4];
#pragma unroll
        for (int nt = 0; nt < 8; nt++)
#pragma unroll
            for (int i = 0; i < 4; i++) s[nt][i] = 0.f;

#pragma unroll
        for (int kk = 0; kk < 4; kk++) {
            uint32_t qa[4];
            uint32_t aoff = sb + (uint32_t)((wid * 16 + (lane & 15)) * APITCH)
                          + kk * 32 + ((lane >> 4) & 1) * 16;
            LDSM4(qa[0], qa[1], qa[2], qa[3], aoff);
#pragma unroll
            for (int np = 0; np < 4; np++) {
                uint32_t boff = st
                              + (uint32_t)((np * 16 + (lane & 7) + ((lane >> 4) & 1) * 8) * APITCH)
                              + kk * 32 + ((lane >> 3) & 1) * 16;
                uint32_t k0r, k1r, k2r, k3r;
                LDSM4(k0r, k1r, k2r, k3r, boff);
                uint32_t bh0[2] = {k0r, k1r}, bh1[2] = {k2r, k3r};
                MMA16816(s[2*np],   qa, bh0);
                MMA16816(s[2*np+1], qa, bh1);
            }
        }

        // ---- scale + causal mask ----
#pragma unroll
        for (int nt = 0; nt < 8; nt++)
#pragma unroll
            for (int i = 0; i < 4; i++) s[nt][i] *= 0.125f;

        if (j0 >= q0) {
#pragma unroll
            for (int nt = 0; nt < 8; nt++) {
                int col = j0 + nt * 8 + (lane & 3) * 2;
                if (col     > r0g)     s[nt][0] = -1e30f;
                if (col + 1 > r0g)     s[nt][1] = -1e30f;
                if (col     > r0g + 8) s[nt][2] = -1e30f;
                if (col + 1 > r0g + 8) s[nt][3] = -1e30f;
            }
        }

        // ---- streaming softmax ----
#pragma unroll
        for (int rh = 0; rh < 2; rh++) {
            float cm = -1e30f;
#pragma unroll
            for (int nt = 0; nt < 8; nt++)
                cm = fmaxf(cm, fmaxf(s[nt][rh*2], s[nt][rh*2+1]));
            cm = fmaxf(cm, __shfl_xor_sync(0xffffffffu, cm, 1));
            cm = fmaxf(cm, __shfl_xor_sync(0xffffffffu, cm, 2));
            float mn = fmaxf(m2[rh], cm);
            float corr = __expf(m2[rh] - mn);
            m2[rh] = mn;
            float rs = 0.f;
#pragma unroll
            for (int nt = 0; nt < 8; nt++) {
                float p0 = __expf(s[nt][rh*2]   - mn);
                float p1 = __expf(s[nt][rh*2+1] - mn);
                s[nt][rh*2] = p0; s[nt][rh*2+1] = p1;
                rs += p0 + p1;
            }
            rs += __shfl_xor_sync(0xffffffffu, rs, 1);
            rs += __shfl_xor_sync(0xffffffffu, rs, 2);
            l2[rh] = l2[rh] * corr + rs;
#pragma unroll
            for (int nt = 0; nt < 8; nt++) {
                o[nt][rh*2]   *= corr;
                o[nt][rh*2+1] *= corr;
            }
        }

        // ---- O += P V ----
#pragma unroll
        for (int kc = 0; kc < 4; kc++) {
            uint32_t ph[4];
            ph[0] = pack2h(s[2*kc][0],   s[2*kc][1]);
            ph[1] = pack2h(s[2*kc][2],   s[2*kc][3]);
            ph[2] = pack2h(s[2*kc+1][0], s[2*kc+1][1]);
            ph[3] = pack2h(s[2*kc+1][2], s[2*kc+1][3]);
#pragma unroll
            for (int np = 0; np < 4; np++) {
                uint32_t voff = st + AVH
                              + (uint32_t)((kc * 16 + (lane & 15)) * APITCH)
                              + (np * 16 + ((lane >> 4) & 1) * 8) * 2;
                uint32_t v0r, v1r, v2r, v3r;
                LDSM4T(v0r, v1r, v2r, v3r, voff);
                uint32_t vh0[2] = {v0r, v1r}, vh1[2] = {v2r, v3r};
                MMA16816(o[2*np],   ph, vh0);
                MMA16816(o[2*np+1], ph, vh1);
            }
        }
    }

    // ---- normalize + write fp16 ----
    float inv0 = 1.f / l2[0], inv1 = 1.f / l2[1];
#pragma unroll
    for (int nt = 0; nt < 8; nt++) {
        int col = h * DHEAD + nt * 8 + (lane & 3) * 2;
        size_t i0 = (size_t)(b * TSEQ + r0g) * DMODEL + col;
        size_t i1 = (size_t)(b * TSEQ + r0g + 8) * DMODEL + col;
        *(__half2*)&Oh[i0] = __floats2half2_rn(o[nt][0] * inv0, o[nt][1] * inv0);
        *(__half2*)&Oh[i1] = __floats2half2_rn(o[nt][2] * inv1, o[nt][3] * inv1);
    }
}

// =================================================================
// LayerNorm; optionally also emits fp16 of the output.
// =================================================================
__global__ __launch_bounds__(256)
void ln_kernel(const float* __restrict__ in, const float* __restrict__ g,
               const float* __restrict__ be, float* __restrict__ out,
               __half* __restrict__ Oh)
{
    const int row = blockIdx.x;
    const int tid = threadIdx.x;
    const float* xr = in + (size_t)row * DMODEL;

    float v0 = xr[tid], v1 = xr[tid + 256], v2 = xr[tid + 512];
    float s = v0 + v1 + v2;
    float s2 = v0 * v0 + v1 * v1 + v2 * v2;

    __shared__ float rs[8], rs2[8], stats[2];
#pragma unroll
    for (int off = 16; off; off >>= 1) {
        s  += __shfl_xor_sync(0xffffffffu, s,  off);
        s2 += __shfl_xor_sync(0xffffffffu, s2, off);
    }
    int w = tid >> 5, lane = tid & 31;
    if (lane == 0) { rs[w] = s; rs2[w] = s2; }
    __syncthreads();
    if (tid == 0) {
        float S = 0.f, S2 = 0.f;
#pragma unroll
        for (int i = 0; i < 8; i++) { S += rs[i]; S2 += rs2[i]; }
        float mean = S * (1.f / DMODEL);
        float var  = S2 * (1.f / DMODEL) - mean * mean;
        stats[0] = mean;
        stats[1] = rsqrtf(var + 1e-5f);
    }
    __syncthreads();
    float mean = stats[0], r = stats[1];
    size_t rb = (size_t)row * DMODEL;
    float vv[3] = {v0, v1, v2};
#pragma unroll
    for (int p = 0; p < 3; p++) {
        int c = tid + p * 256;
        float y = (vv[p] - mean) * r * g[c] + be[c];
        out[rb + c] = y;
        if (Oh) Oh[rb + c] = __float2half_rn(y);
    }
}

// =================================================================
// Host launch
// =================================================================
extern "C" void kernel_launch(void* const* d_in, const int* in_sizes, int n_in,
                              void* d_out, int out_size)
{
    const float* x  = (const float*)d_in[0];
    const float* wq = (const float*)d_in[1];
    const float* bq = (const float*)d_in[2];
    const float* wk = (const float*)d_in[3];
    const float* bk = (const float*)d_in[4];
    const float* wv = (const float*)d_in[5];
    const float* bv = (const float*)d_in[6];
    const float* wo = (const float*)d_in[7];
    const float* bo = (const float*)d_in[8];
    const float* w1 = (const float*)d_in[9];
    const float* b1 = (const float*)d_in[10];
    const float* w2 = (const float*)d_in[11];
    const float* b2 = (const float*)d_in[12];
    const float* g1 = (const float*)d_in[13];
    const float* be1= (const float*)d_in[14];
    const float* g2 = (const float*)d_in[15];
    const float* be2= (const float*)d_in[16];
    float* out = (float*)d_out;

    float *R1, *H, *R2;
    __half *Qh, *Kh, *Vh, *Act, *FF, *W;
    cudaGetSymbolAddress((void**)&R1,  g_R1);
    cudaGetSymbolAddress((void**)&H,   g_H);
    cudaGetSymbolAddress((void**)&R2,  g_R2);
    cudaGetSymbolAddress((void**)&Qh,  g_qh);
    cudaGetSymbolAddress((void**)&Kh,  g_kh);
    cudaGetSymbolAddress((void**)&Vh,  g_vh);
    cudaGetSymbolAddress((void**)&Act, g_act);
    cudaGetSymbolAddress((void**)&FF,  g_ff);
    cudaGetSymbolAddress((void**)&W,   g_w);

    cudaFuncSetAttribute(attn_mma, cudaFuncAttributeMaxDynamicSharedMemorySize, ATT_SMEM);
    cudaFuncSetAttribute(gemm_mma, cudaFuncAttributeMaxDynamicSharedMemorySize, GEMM_SMEM);

    // weight transpose to fp16 [N,K]
    dim3 tb(32, 8);
    const float*  wsrc[6] = {wq, wk, wv, wo, w1, w2};
    const size_t  offs[6] = {WQ_OFF, WK_OFF, WV_OFF, WO_OFF, W1_OFF, W2_OFF};
    const int     wkd[6]  = {768, 768, 768, 768, 768, 3072};
    const int     wnd[6]  = {768, 768, 768, 768, 3072, 768};
    for (int i = 0; i < 6; i++)
        wsplit_kernel<<<dim3(wkd[i] / 32, wnd[i] / 32), tb>>>(
            wsrc[i], W + offs[i], wkd[i], wnd[i]);

    // x -> fp16
    asplit_kernel<<<MTOK * DMODEL / 1024, 256>>>(x, Act);

    dim3 gD(DMODEL / 128, MTOK / 128);  // (6, 64)
    dim3 gF(DFF / 128,    MTOK / 128);  // (24, 64)

    // QKV projections
    gemm_mma<<<gD, 256, GEMM_SMEM>>>(Act, W + WQ_OFF, bq, nullptr, nullptr, Qh, DMODEL, DMODEL, 0);
    gemm_mma<<<gD, 256, GEMM_SMEM>>>(Act, W + WK_OFF, bk, nullptr, nullptr, Kh, DMODEL, DMODEL, 0);
    gemm_mma<<<gD, 256, GEMM_SMEM>>>(Act, W + WV_OFF, bv, nullptr, nullptr, Vh, DMODEL, DMODEL, 0);

    // causal flash attention -> attn out fp16 into Act
    attn_mma<<<dim3(TSEQ / 128, NHEADS, BBATCH), 256, ATT_SMEM>>>(Qh, Kh, Vh, Act);

    // output projection + residual(x), LN1 (emits H fp16 into Act)
    gemm_mma<<<gD, 256, GEMM_SMEM>>>(Act, W + WO_OFF, bo, x, R1, nullptr, DMODEL, DMODEL, 0);
    ln_kernel<<<MTOK, 256>>>(R1, g1, be1, H, Act);

    // FFN: W1 (+relu) -> FF fp16; W2 + residual(H)
    gemm_mma<<<gF, 256, GEMM_SMEM>>>(Act, W + W1_OFF, b1, nullptr, nullptr, FF, DFF, DMODEL, 1);
    gemm_mma<<<gD, 256, GEMM_SMEM>>>(FF,  W + W2_OFF, b2, H, R2, nullptr, DMODEL, DFF, 0);

    // LN2 -> output
    ln_kernel<<<MTOK, 256>>>(R2, g2, be2, out, nullptr);
}

// round 15
// speedup vs baseline: 6.6884x; 1.2084x over previous
#include <cuda_runtime.h>
#include <cuda_fp16.h>
#include <stdint.h>
#include <math.h>

// ---------------- problem constants ----------------
#define DMODEL 768
#define NHEADS 12
#define DHEAD  64
#define DFF    3072
#define BBATCH 2
#define TSEQ   4096
#define MTOK   (BBATCH * TSEQ)   // 8192 tokens

// weight (transposed [N,K], fp16) offsets inside g_w
#define WQ_OFF 0
#define WK_OFF (768*768)
#define WV_OFF (2*768*768)
#define WO_OFF (3*768*768)
#define W1_OFF (4*768*768)                 // [3072][768]
#define W2_OFF (4*768*768 + 768*3072)      // [768][3072]
#define WTOT   (4*768*768 + 2*768*3072)

// ---------------- scratch (device globals; no allocation allowed) ----------------
__device__ float g_R1 [MTOK * DMODEL];
__device__ float g_H  [MTOK * DMODEL];
__device__ float g_R2 [MTOK * DMODEL];
__device__ __half g_qh [MTOK * DMODEL];
__device__ __half g_kh [MTOK * DMODEL];
__device__ __half g_vh [MTOK * DMODEL];
__device__ __half g_act[MTOK * DMODEL];
__device__ __half g_ff [MTOK * DFF];
__device__ __half g_w  [WTOT];

// ---------------- helpers ----------------
__device__ __forceinline__ uint32_t smem_u32(const void* p) {
    uint32_t a;
    asm("{ .reg .u64 t; cvta.to.shared.u64 t, %1; cvt.u32.u64 %0, t; }" : "=r"(a) : "l"(p));
    return a;
}
__device__ __forceinline__ void cp16(uint32_t d, const void* s) {
    asm volatile("cp.async.cg.shared.global [%0], [%1], 16;" :: "r"(d), "l"(s));
}
#define CP_COMMIT() asm volatile("cp.async.commit_group;" ::: "memory")
#define CP_WAIT1()  asm volatile("cp.async.wait_group 1;"  ::: "memory")

#define LDSM4(r0, r1, r2, r3, addr) \
    asm volatile("ldmatrix.sync.aligned.m8n8.x4.shared.b16 {%0,%1,%2,%3}, [%4];" \
        : "=r"(r0), "=r"(r1), "=r"(r2), "=r"(r3) : "r"(addr))
#define LDSM4T(r0, r1, r2, r3, addr) \
    asm volatile("ldmatrix.sync.aligned.m8n8.x4.trans.shared.b16 {%0,%1,%2,%3}, [%4];" \
        : "=r"(r0), "=r"(r1), "=r"(r2), "=r"(r3) : "r"(addr))

#define MMA16816(c, a, b) \
    asm volatile("mma.sync.aligned.m16n8k16.row.col.f32.f16.f16.f32 " \
        "{%0,%1,%2,%3},{%4,%5,%6,%7},{%8,%9},{%0,%1,%2,%3};" \
        : "+f"((c)[0]), "+f"((c)[1]), "+f"((c)[2]), "+f"((c)[3]) \
        : "r"((a)[0]), "r"((a)[1]), "r"((a)[2]), "r"((a)[3]), \
          "r"((b)[0]), "r"((b)[1]))

__device__ __forceinline__ uint32_t pack2h(float a, float b) {
    __half2 h = __floats2half2_rn(a, b);
    return *(uint32_t*)&h;
}

// =================================================================
// mma.sync GEMM (pure fp16): C = A @ Bt^T (+bias)(+res)(+relu)
// fp32 accum. Block 128x128, BK=32, 256 threads. 3-stage cp.async ring,
// one __syncthreads per k-step. qkv mode splits output cols into 3 dests.
// =================================================================
#define BKG   32
#define ROWB  80
#define TILEB 10240
#define STAGEB (2 * TILEB)            // A, B
#define GEMM_SMEM (3 * STAGEB)        // 61440 B

__device__ __forceinline__ void load_stage(
    uint32_t st, const __half* A, const __half* B,
    int bm, int bn, int k0, int K, int tid)
{
#pragma unroll
    for (int i = 0; i < 4; i++) {
        int idx = tid + i * 256;          // 0..1023
        int t   = idx >> 9;               // 0=A 1=B
        int rem = idx & 511;
        int r   = rem >> 2;               // row 0..127
        int kc  = (rem & 3) * 8;
        uint32_t so = (uint32_t)(r * ROWB + kc * 2);
        const __half* src = t ? B : A;
        int base = t ? bn : bm;
        cp16(st + t * TILEB + so, src + (size_t)(base + r) * K + k0 + kc);
    }
}

__global__ __launch_bounds__(256, 2)
void gemm_mma(const __half* __restrict__ A, const __half* __restrict__ B,
              const float* __restrict__ bias, const float* __restrict__ res,
              float* __restrict__ C, __half* __restrict__ Chf,
              int N, int K, int relu, int qkv,
              const float* __restrict__ bias1, const float* __restrict__ bias2,
              __half* __restrict__ Chf1, __half* __restrict__ Chf2)
{
    extern __shared__ char smem[];
    const uint32_t sb = smem_u32(smem);
    const int tid = threadIdx.x;
    const int wid = tid >> 5, lane = tid & 31;
    const int wm = wid & 1;
    const int wn = wid >> 1;
    const int bm = blockIdx.y * 128, bn = blockIdx.x * 128;

    float acc[4][4][4];
#pragma unroll
    for (int mt = 0; mt < 4; mt++)
#pragma unroll
        for (int nt = 0; nt < 4; nt++)
#pragma unroll
            for (int i = 0; i < 4; i++) acc[mt][nt][i] = 0.f;

    const int nk = K / BKG;   // >= 24 always
    load_stage(sb, A, B, bm, bn, 0, K, tid);
    CP_COMMIT();
    load_stage(sb + STAGEB, A, B, bm, bn, BKG, K, tid);
    CP_COMMIT();

    for (int ks = 0; ks < nk; ks++) {
        CP_WAIT1();
        __syncthreads();
        if (ks + 2 < nk)
            load_stage(sb + ((ks + 2) % 3) * STAGEB, A, B, bm, bn, (ks + 2) * BKG, K, tid);
        CP_COMMIT();

        const uint32_t st = sb + (ks % 3) * STAGEB;
#pragma unroll
        for (int kk = 0; kk < 2; kk++) {
            uint32_t af[4][4];
            uint32_t aoff = st + (uint32_t)((wm * 64 + (lane & 15)) * ROWB)
                          + kk * 32 + ((lane >> 4) & 1) * 16;
#pragma unroll
            for (int mt = 0; mt < 4; mt++)
                LDSM4(af[mt][0], af[mt][1], af[mt][2], af[mt][3], aoff + mt * 16 * ROWB);

            uint32_t bf[4][2];
            uint32_t boff = st + TILEB
                          + (uint32_t)((wn * 32 + (lane & 7) + ((lane >> 4) & 1) * 8) * ROWB)
                          + kk * 32 + ((lane >> 3) & 1) * 16;
#pragma unroll
            for (int np = 0; np < 2; np++) {
                uint32_t r0, r1, r2, r3;
                LDSM4(r0, r1, r2, r3, boff + np * 16 * ROWB);
                bf[2*np][0] = r0; bf[2*np][1] = r1; bf[2*np+1][0] = r2; bf[2*np+1][1] = r3;
            }
#pragma unroll
            for (int mt = 0; mt < 4; mt++)
#pragma unroll
                for (int nt = 0; nt < 4; nt++)
                    MMA16816(acc[mt][nt], af[mt], bf[nt]);
        }
    }
    __syncthreads();

    // ---- epilogue (qkv mode: route by output-column segment) ----
    int bnl = bn, Nol = N;
    const float* bi = bias;
    __half* dst = Chf;
    if (qkv) {
        int seg = bn / 768;
        bnl = bn - seg * 768;
        Nol = 768;
        bi  = (seg == 0) ? bias : (seg == 1) ? bias1 : bias2;
        dst = (seg == 0) ? Chf  : (seg == 1) ? Chf1  : Chf2;
    }

#pragma unroll
    for (int mt = 0; mt < 4; mt++)
#pragma unroll
        for (int nt = 0; nt < 4; nt++) {
            int row = bm + wm * 64 + mt * 16 + (lane >> 2);
            int col = bnl + wn * 32 + nt * 8 + (lane & 3) * 2;
            float b0 = bi[col], b1 = bi[col + 1];
#pragma unroll
            for (int half = 0; half < 2; half++) {
                int r = row + half * 8;
                size_t idx = (size_t)r * Nol + col;
                float v0 = acc[mt][nt][half * 2 + 0] + b0;
                float v1 = acc[mt][nt][half * 2 + 1] + b1;
                if (res) {
                    float2 rv = *(const float2*)&res[idx];
                    v0 += rv.x; v1 += rv.y;
                }
                if (relu) { v0 = fmaxf(v0, 0.f); v1 = fmaxf(v1, 0.f); }
                if (C) { float2 o = make_float2(v0, v1); *(float2*)&C[idx] = o; }
                if (dst) *(__half2*)&dst[idx] = __floats2half2_rn(v0, v1);
            }
        }
}

// =================================================================
// Weight transpose: W[K,N] fp32 -> T[N,K] fp16
// =================================================================
__global__ void wsplit_kernel(const float* __restrict__ W, __half* __restrict__ T,
                              int Kd, int Nd)
{
    __shared__ float t[32][33];
    int k0 = blockIdx.x * 32, n0 = blockIdx.y * 32;
    int tx = threadIdx.x, ty = threadIdx.y;
    for (int i = ty; i < 32; i += 8)
        t[i][tx] = W[(size_t)(k0 + i) * Nd + n0 + tx];
    __syncthreads();
    for (int i = ty; i < 32; i += 8)
        T[(size_t)(n0 + i) * Kd + k0 + tx] = __float2half_rn(t[tx][i]);
}

// activation fp32 -> fp16
__global__ void asplit_kernel(const float* __restrict__ A, __half* __restrict__ Ah)
{
    int i = (blockIdx.x * blockDim.x + threadIdx.x) * 4;
    float4 v = *(const float4*)&A[i];
    *(__half2*)&Ah[i]     = __floats2half2_rn(v.x, v.y);
    *(__half2*)&Ah[i + 2] = __floats2half2_rn(v.z, v.w);
}

// =================================================================
// Flash attention (causal) on mma.sync, pure fp16, fp32 softmax.
// 128 queries x (head,batch); 8 warps; 64-key chunks; 3-stage cp.async ring.
// =================================================================
#define APITCH   144
#define AST_OFF  18432               // Q: 128*144
#define AVH 9216
#define AST_SZ   18432               // K + V tiles
#define ATT_SMEM (AST_OFF + 3 * AST_SZ)   // 73728 B

__device__ __forceinline__ void att_load_kv(
    uint32_t stbase, const __half* Kh, const __half* Vh,
    int b, int h, int j0, int tid)
{
#pragma unroll
    for (int i = 0; i < 4; i++) {
        int idx = tid + i * 256;          // 0..1023
        int t   = idx >> 9;               // 0=K 1=V
        int rem = idx & 511;
        int r   = rem >> 3;               // row 0..63
        int c   = (rem & 7) * 8;
        size_t go = (size_t)(b * TSEQ + j0 + r) * DMODEL + h * DHEAD + c;
        cp16(stbase + t * AVH + r * APITCH + c * 2, (t ? Vh : Kh) + go);
    }
}

__global__ __launch_bounds__(256, 1)
void attn_mma(const __half* __restrict__ Qh,
              const __half* __restrict__ Kh, const __half* __restrict__ Vh,
              __half* __restrict__ Oh)
{
    extern __shared__ char smem[];
    const uint32_t sb = smem_u32(smem);
    const int tid = threadIdx.x;
    const int wid = tid >> 5, lane = tid & 31;
    const int q0 = (gridDim.x - 1 - blockIdx.x) * 128;   // long blocks first
    const int h  = blockIdx.y;
    const int b  = blockIdx.z;

    // ---- load Q tile (own group) ----
#pragma unroll
    for (int i = 0; i < 4; i++) {
        int idx = tid + i * 256;
        int r   = idx >> 3;
        int c   = (idx & 7) * 8;
        size_t go = (size_t)(b * TSEQ + q0 + r) * DMODEL + h * DHEAD + c;
        cp16(sb + r * APITCH + c * 2, Qh + go);
    }
    CP_COMMIT();

    const int nch = q0 / 64 + 2;      // >= 2 always
    att_load_kv(sb + AST_OFF, Kh, Vh, b, h, 0, tid);
    CP_COMMIT();
    att_load_kv(sb + AST_OFF + AST_SZ, Kh, Vh, b, h, 64, tid);
    CP_COMMIT();

    float m2[2] = {-1e30f, -1e30f};
    float l2[2] = {0.f, 0.f};
    float o[8][4];
#pragma unroll
    for (int nt = 0; nt < 8; nt++)
#pragma unroll
        for (int i = 0; i < 4; i++) o[nt][i] = 0.f;

    const int r0g = q0 + wid * 16 + (lane >> 2);

    for (int ci = 0; ci < nch; ci++) {
        CP_WAIT1();
        __syncthreads();
        if (ci + 2 < nch)
            att_load_kv(sb + AST_OFF + ((ci + 2) % 3) * AST_SZ,
                        Kh, Vh, b, h, (ci + 2) * 64, tid);
        CP_COMMIT();

        const uint32_t st = sb + AST_OFF + (ci % 3) * AST_SZ;
        const int j0 = ci * 64;

        // ---- S = Q K^T ----
        float s[8][4];
#pragma unroll
        for (int nt = 0; nt < 8; nt++)
#pragma unroll
            for (int i = 0; i < 4; i++) s[nt][i] = 0.f;

#pragma unroll
        for (int kk = 0; kk < 4; kk++) {
            uint32_t qa[4];
            uint32_t aoff = sb + (uint32_t)((wid * 16 + (lane & 15)) * APITCH)
                          + kk * 32 + ((lane >> 4) & 1) * 16;
            LDSM4(qa[0], qa[1], qa[2], qa[3], aoff);
#pragma unroll
            for (int np = 0; np < 4; np++) {
                uint32_t boff = st
                              + (uint32_t)((np * 16 + (lane & 7) + ((lane >> 4) & 1) * 8) * APITCH)
                              + kk * 32 + ((lane >> 3) & 1) * 16;
                uint32_t k0r, k1r, k2r, k3r;
                LDSM4(k0r, k1r, k2r, k3r, boff);
                uint32_t bh0[2] = {k0r, k1r}, bh1[2] = {k2r, k3r};
                MMA16816(s[2*np],   qa, bh0);
                MMA16816(s[2*np+1], qa, bh1);
            }
        }

        // ---- scale + causal mask ----
#pragma unroll
        for (int nt = 0; nt < 8; nt++)
#pragma unroll
            for (int i = 0; i < 4; i++) s[nt][i] *= 0.125f;

        if (j0 >= q0) {
#pragma unroll
            for (int nt = 0; nt < 8; nt++) {
                int col = j0 + nt * 8 + (lane & 3) * 2;
                if (col     > r0g)     s[nt][0] = -1e30f;
                if (col + 1 > r0g)     s[nt][1] = -1e30f;
                if (col     > r0g + 8) s[nt][2] = -1e30f;
                if (col + 1 > r0g + 8) s[nt][3] = -1e30f;
            }
        }

        // ---- streaming softmax ----
#pragma unroll
        for (int rh = 0; rh < 2; rh++) {
            float cm = -1e30f;
#pragma unroll
            for (int nt = 0; nt < 8; nt++)
                cm = fmaxf(cm, fmaxf(s[nt][rh*2], s[nt][rh*2+1]));
            cm = fmaxf(cm, __shfl_xor_sync(0xffffffffu, cm, 1));
            cm = fmaxf(cm, __shfl_xor_sync(0xffffffffu, cm, 2));
            float mn = fmaxf(m2[rh], cm);
            float corr = __expf(m2[rh] - mn);
            m2[rh] = mn;
            float rs = 0.f;
#pragma unroll
            for (int nt = 0; nt < 8; nt++) {
                float p0 = __expf(s[nt][rh*2]   - mn);
                float p1 = __expf(s[nt][rh*2+1] - mn);
                s[nt][rh*2] = p0; s[nt][rh*2+1] = p1;
                rs += p0 + p1;
            }
            rs += __shfl_xor_sync(0xffffffffu, rs, 1);
            rs += __shfl_xor_sync(0xffffffffu, rs, 2);
            l2[rh] = l2[rh] * corr + rs;
#pragma unroll
            for (int nt = 0; nt < 8; nt++) {
                o[nt][rh*2]   *= corr;
                o[nt][rh*2+1] *= corr;
            }
        }

        // ---- O += P V ----
#pragma unroll
        for (int kc = 0; kc < 4; kc++) {
            uint32_t ph[4];
            ph[0] = pack2h(s[2*kc][0],   s[2*kc][1]);
            ph[1] = pack2h(s[2*kc][2],   s[2*kc][3]);
            ph[2] = pack2h(s[2*kc+1][0], s[2*kc+1][1]);
            ph[3] = pack2h(s[2*kc+1][2], s[2*kc+1][3]);
#pragma unroll
            for (int np = 0; np < 4; np++) {
                uint32_t voff = st + AVH
                              + (uint32_t)((kc * 16 + (lane & 15)) * APITCH)
                              + (np * 16 + ((lane >> 4) & 1) * 8) * 2;
                uint32_t v0r, v1r, v2r, v3r;
                LDSM4T(v0r, v1r, v2r, v3r, voff);
                uint32_t vh0[2] = {v0r, v1r}, vh1[2] = {v2r, v3r};
                MMA16816(o[2*np],   ph, vh0);
                MMA16816(o[2*np+1], ph, vh1);
            }
        }
    }

    // ---- normalize + write fp16 ----
    float inv0 = 1.f / l2[0], inv1 = 1.f / l2[1];
#pragma unroll
    for (int nt = 0; nt < 8; nt++) {
        int col = h * DHEAD + nt * 8 + (lane & 3) * 2;
        size_t i0 = (size_t)(b * TSEQ + r0g) * DMODEL + col;
        size_t i1 = (size_t)(b * TSEQ + r0g + 8) * DMODEL + col;
        *(__half2*)&Oh[i0] = __floats2half2_rn(o[nt][0] * inv0, o[nt][1] * inv0);
        *(__half2*)&Oh[i1] = __floats2half2_rn(o[nt][2] * inv1, o[nt][3] * inv1);
    }
}

// =================================================================
// LayerNorm; optionally also emits fp16 of the output.
// =================================================================
__global__ __launch_bounds__(256)
void ln_kernel(const float* __restrict__ in, const float* __restrict__ g,
               const float* __restrict__ be, float* __restrict__ out,
               __half* __restrict__ Oh)
{
    const int row = blockIdx.x;
    const int tid = threadIdx.x;
    const float* xr = in + (size_t)row * DMODEL;

    float v0 = xr[tid], v1 = xr[tid + 256], v2 = xr[tid + 512];
    float s = v0 + v1 + v2;
    float s2 = v0 * v0 + v1 * v1 + v2 * v2;

    __shared__ float rs[8], rs2[8], stats[2];
#pragma unroll
    for (int off = 16; off; off >>= 1) {
        s  += __shfl_xor_sync(0xffffffffu, s,  off);
        s2 += __shfl_xor_sync(0xffffffffu, s2, off);
    }
    int w = tid >> 5, lane = tid & 31;
    if (lane == 0) { rs[w] = s; rs2[w] = s2; }
    __syncthreads();
    if (tid == 0) {
        float S = 0.f, S2 = 0.f;
#pragma unroll
        for (int i = 0; i < 8; i++) { S += rs[i]; S2 += rs2[i]; }
        float mean = S * (1.f / DMODEL);
        float var  = S2 * (1.f / DMODEL) - mean * mean;
        stats[0] = mean;
        stats[1] = rsqrtf(var + 1e-5f);
    }
    __syncthreads();
    float mean = stats[0], r = stats[1];
    size_t rb = (size_t)row * DMODEL;
    float vv[3] = {v0, v1, v2};
#pragma unroll
    for (int p = 0; p < 3; p++) {
        int c = tid + p * 256;
        float y = (vv[p] - mean) * r * g[c] + be[c];
        out[rb + c] = y;
        if (Oh) Oh[rb + c] = __float2half_rn(y);
    }
}

// =================================================================
// Host launch
// =================================================================
extern "C" void kernel_launch(void* const* d_in, const int* in_sizes, int n_in,
                              void* d_out, int out_size)
{
    const float* x  = (const float*)d_in[0];
    const float* wq = (const float*)d_in[1];
    const float* bq = (const float*)d_in[2];
    const float* wk = (const float*)d_in[3];
    const float* bk = (const float*)d_in[4];
    const float* wv = (const float*)d_in[5];
    const float* bv = (const float*)d_in[6];
    const float* wo = (const float*)d_in[7];
    const float* bo = (const float*)d_in[8];
    const float* w1 = (const float*)d_in[9];
    const float* b1 = (const float*)d_in[10];
    const float* w2 = (const float*)d_in[11];
    const float* b2 = (const float*)d_in[12];
    const float* g1 = (const float*)d_in[13];
    const float* be1= (const float*)d_in[14];
    const float* g2 = (const float*)d_in[15];
    const float* be2= (const float*)d_in[16];
    float* out = (float*)d_out;

    float *R1, *H, *R2;
    __half *Qh, *Kh, *Vh, *Act, *FF, *W;
    cudaGetSymbolAddress((void**)&R1,  g_R1);
    cudaGetSymbolAddress((void**)&H,   g_H);
    cudaGetSymbolAddress((void**)&R2,  g_R2);
    cudaGetSymbolAddress((void**)&Qh,  g_qh);
    cudaGetSymbolAddress((void**)&Kh,  g_kh);
    cudaGetSymbolAddress((void**)&Vh,  g_vh);
    cudaGetSymbolAddress((void**)&Act, g_act);
    cudaGetSymbolAddress((void**)&FF,  g_ff);
    cudaGetSymbolAddress((void**)&W,   g_w);

    cudaFuncSetAttribute(attn_mma, cudaFuncAttributeMaxDynamicSharedMemorySize, ATT_SMEM);
    cudaFuncSetAttribute(gemm_mma, cudaFuncAttributeMaxDynamicSharedMemorySize, GEMM_SMEM);

    // weight transpose to fp16 [N,K]
    dim3 tb(32, 8);
    const float*  wsrc[6] = {wq, wk, wv, wo, w1, w2};
    const size_t  offs[6] = {WQ_OFF, WK_OFF, WV_OFF, WO_OFF, W1_OFF, W2_OFF};
    const int     wkd[6]  = {768, 768, 768, 768, 768, 3072};
    const int     wnd[6]  = {768, 768, 768, 768, 3072, 768};
    for (int i = 0; i < 6; i++)
        wsplit_kernel<<<dim3(wkd[i] / 32, wnd[i] / 32), tb>>>(
            wsrc[i], W + offs[i], wkd[i], wnd[i]);

    // x -> fp16
    asplit_kernel<<<MTOK * DMODEL / 1024, 256>>>(x, Act);

    dim3 gQKV((3 * DMODEL) / 128, MTOK / 128);  // (18, 64)
    dim3 gD(DMODEL / 128, MTOK / 128);          // (6, 64)
    dim3 gF(DFF / 128,    MTOK / 128);          // (24, 64)

    // fused QKV projection (weights contiguous as [2304][768])
    gemm_mma<<<gQKV, 256, GEMM_SMEM>>>(Act, W + WQ_OFF, bq, nullptr, nullptr, Qh,
                                       3 * DMODEL, DMODEL, 0, 1, bk, bv, Kh, Vh);

    // causal flash attention -> attn out fp16 into Act
    attn_mma<<<dim3(TSEQ / 128, NHEADS, BBATCH), 256, ATT_SMEM>>>(Qh, Kh, Vh, Act);

    // output projection + residual(x), LN1 (emits H fp16 into Act)
    gemm_mma<<<gD, 256, GEMM_SMEM>>>(Act, W + WO_OFF, bo, x, R1, nullptr,
                                     DMODEL, DMODEL, 0, 0, nullptr, nullptr, nullptr, nullptr);
    ln_kernel<<<MTOK, 256>>>(R1, g1, be1, H, Act);

    // FFN: W1 (+relu) -> FF fp16; W2 + residual(H)
    gemm_mma<<<gF, 256, GEMM_SMEM>>>(Act, W + W1_OFF, b1, nullptr, nullptr, FF,
                                     DFF, DMODEL, 1, 0, nullptr, nullptr, nullptr, nullptr);
    gemm_mma<<<gD, 256, GEMM_SMEM>>>(FF,  W + W2_OFF, b2, H, R2, nullptr,
                                     DMODEL, DFF, 0, 0, nullptr, nullptr, nullptr, nullptr);

    // LN2 -> output
    ln_kernel<<<MTOK, 256>>>(R2, g2, be2, out, nullptr);
}